// round 1
// baseline (speedup 1.0000x reference)
#include <cuda_runtime.h>
#include <math.h>

// ---------------- problem constants ----------------
#define HH 64
#define WW 64
#define PP 4096          // H*W
#define CC 512
#define CGC 128
#define GG 4
#define KK 9
#define NH 8
#define DH 64
#define NPT 2048         // n selected points
#define NSLOT 36         // G*K

// d_out layout: y (2048*512) | attn (8*2048*9) | xr_sel (2048*36*512) | sig (2048)
#define Y_OFF   0L
#define ATT_OFF 1048576L
#define XR_OFF  1196032L
#define SIG_OFF 38944768L

// ---------------- scratch (device globals; no runtime alloc) ----------------
__device__ float  g_xT  [(long)PP * CC];       // x transposed: (pixel, channel)
__device__ float  g_qT  [(long)PP * CC];       // q: (pixel, channel)
__device__ float  g_t1  [(long)GG * PP * CGC]; // (g, pixel, cc)
__device__ float  g_t2  [(long)GG * PP * CGC];
__device__ float2 g_meta[(long)NPT * NSLOT];   // (gy, gx) per (j, g*9+k)
__device__ float  g_qsel[(long)NPT * CC];      // q at selected points (j, c)
__device__ float  g_qk  [(long)NPT * 4096];    // (j, h*512+c)
__device__ float  g_xsagg[(long)NPT * 4096];   // (j, h*512+c)
__device__ float  g_outT[(long)NPT * CC];      // (j, h*64+d)

// ---------------- transpose x (C,P) -> xT (P,C) ----------------
__global__ void transpose_kernel(const float* __restrict__ x)
{
    __shared__ float tile[32][33];
    int pb = blockIdx.x * 32;
    int cb = blockIdx.y * 32;
    int tx = threadIdx.x, ty = threadIdx.y;
    #pragma unroll
    for (int i = 0; i < 32; i += 8)
        tile[ty + i][tx] = x[(long)(cb + ty + i) * PP + pb + tx];
    __syncthreads();
    #pragma unroll
    for (int i = 0; i < 32; i += 8)
        g_xT[(long)(pb + ty + i) * CC + cb + tx] = tile[tx][ty + i];
}

// ---------------- generic SGEMM: C(M,N) = A(M,K) * B(K,N) [+bias] ----------------
// TRANSB: B[k,n] = Bb[n*ldb + k]
template<int TRANSB>
__global__ void sgemm_kernel(const float* __restrict__ A, const float* __restrict__ B,
                             float* __restrict__ C, const float* __restrict__ bias,
                             int M, int N, int Kd, int lda, int ldb, int ldc,
                             long aOff, long bOff, long cOff, long biasOff)
{
    const int BM = 128, BN = 64, BK = 16;
    __shared__ __align__(16) float As[BK][BM + 4];
    __shared__ __align__(16) float Bs[BK][BN + 4];
    int z = blockIdx.z;
    A += (long)z * aOff;
    B += (long)z * bOff;
    C += (long)z * cOff;
    if (bias) bias += (long)z * biasOff;

    int m0 = blockIdx.y * BM;
    int n0 = blockIdx.x * BN;
    int tid = threadIdx.x;          // 128 threads
    int tm = tid >> 3;              // 0..15
    int tn = tid & 7;               // 0..7

    float acc[8][8];
    #pragma unroll
    for (int i = 0; i < 8; i++)
        #pragma unroll
        for (int j = 0; j < 8; j++) acc[i][j] = 0.f;

    for (int k0 = 0; k0 < Kd; k0 += BK) {
        #pragma unroll
        for (int j = 0; j < 16; j++) {
            int e = tid + j * 128;
            int m = e >> 4, k = e & 15;
            As[k][m] = A[(long)(m0 + m) * lda + k0 + k];
        }
        if (!TRANSB) {
            #pragma unroll
            for (int j = 0; j < 8; j++) {
                int e = tid + j * 128;
                int n = e & 63, k = e >> 6;
                Bs[k][n] = B[(long)(k0 + k) * ldb + n0 + n];
            }
        } else {
            #pragma unroll
            for (int j = 0; j < 8; j++) {
                int e = tid + j * 128;
                int k = e & 15, n = e >> 4;
                Bs[k][n] = B[(long)(n0 + n) * ldb + k0 + k];
            }
        }
        __syncthreads();
        #pragma unroll
        for (int kk = 0; kk < BK; kk++) {
            float4 a0 = *(const float4*)&As[kk][tm * 8];
            float4 a1 = *(const float4*)&As[kk][tm * 8 + 4];
            float4 b0 = *(const float4*)&Bs[kk][tn * 8];
            float4 b1 = *(const float4*)&Bs[kk][tn * 8 + 4];
            float ra[8] = {a0.x, a0.y, a0.z, a0.w, a1.x, a1.y, a1.z, a1.w};
            float rb[8] = {b0.x, b0.y, b0.z, b0.w, b1.x, b1.y, b1.z, b1.w};
            #pragma unroll
            for (int i = 0; i < 8; i++)
                #pragma unroll
                for (int j = 0; j < 8; j++)
                    acc[i][j] += ra[i] * rb[j];
        }
        __syncthreads();
    }
    #pragma unroll
    for (int i = 0; i < 8; i++) {
        int m = m0 + tm * 8 + i;
        #pragma unroll
        for (int j = 0; j < 8; j++) {
            int n = n0 + tn * 8 + j;
            float v = acc[i][j];
            if (bias) v += bias[n];
            C[(long)m * ldc + n] = v;
        }
    }
}

// ---------------- depthwise3x3 + LayerNorm(channels) + GELU ----------------
// in addressing: in[g*gStride + pixel*pixStride + cc], out (g, pixel, cc)
__global__ void dw_ln_gelu_kernel(const float* __restrict__ in, float* __restrict__ outp,
                                  const float* __restrict__ w, const float* __restrict__ cb,
                                  const float* __restrict__ gamma, const float* __restrict__ beta,
                                  long gStride, int pixStride)
{
    int p = blockIdx.x;
    int g = blockIdx.y;
    int cc = threadIdx.x;           // 128
    int h = p >> 6, wx = p & 63;
    const float* base = in + (long)g * gStride + cc;

    float acc = cb[cc];
    #pragma unroll
    for (int dy = 0; dy < 3; dy++) {
        int yy = h + dy - 1;
        if ((unsigned)yy < 64u) {
            #pragma unroll
            for (int dx = 0; dx < 3; dx++) {
                int xx = wx + dx - 1;
                if ((unsigned)xx < 64u)
                    acc += base[(long)(yy * 64 + xx) * pixStride] * w[cc * 9 + dy * 3 + dx];
            }
        }
    }
    // LayerNorm over 128 channels
    float s1 = acc, s2 = acc * acc;
    #pragma unroll
    for (int o = 16; o > 0; o >>= 1) {
        s1 += __shfl_xor_sync(0xffffffffu, s1, o);
        s2 += __shfl_xor_sync(0xffffffffu, s2, o);
    }
    __shared__ float r1[4], r2[4];
    int warp = cc >> 5, lane = cc & 31;
    if (lane == 0) { r1[warp] = s1; r2[warp] = s2; }
    __syncthreads();
    float t1s = r1[0] + r1[1] + r1[2] + r1[3];
    float t2s = r2[0] + r2[1] + r2[2] + r2[3];
    float mean = t1s * (1.f / 128.f);
    float var  = fmaxf(t2s * (1.f / 128.f) - mean * mean, 0.f);
    float nv = (acc - mean) * rsqrtf(var + 1e-5f) * gamma[cc] + beta[cc];
    float ge = 0.5f * nv * (1.f + erff(nv * 0.70710678118654752f));
    outp[((long)g * PP + p) * CGC + cc] = ge;
}

// ---------------- offsets + sample coords at selected points; gather q_sel ----------------
__global__ void offset_kernel(const int* __restrict__ idx, const float* __restrict__ ow3)
{
    int j = blockIdx.x;
    int tid = threadIdx.x;          // 128
    __shared__ float tv[128];
    __shared__ float offv[18];
    int iy = idx[2 * j], ix = idx[2 * j + 1];
    int p = iy * 64 + ix;

    // gather q at this point (512 contiguous floats)
    const float4* qrow = (const float4*)(g_qT + (long)p * CC);
    float4* qs = (float4*)(g_qsel + (long)j * CC);
    qs[tid] = qrow[tid];

    for (int g = 0; g < GG; g++) {
        tv[tid] = g_t2[((long)g * PP + p) * CGC + tid];
        __syncthreads();
        if (tid < 18) {
            float s = 0.f;
            #pragma unroll 8
            for (int c = 0; c < 128; c++) s += tv[c] * ow3[tid * 128 + c];
            offv[tid] = s;
        }
        __syncthreads();
        if (tid < KK) {
            int k = tid, dy = k / 3, dx = k % 3;
            float oy = tanhf(offv[2 * k])     * (1.f / 32.f);  // tanh * (1/64) * 2
            float ox = tanhf(offv[2 * k + 1]) * (1.f / 32.f);
            int iyc = min(max(iy + dy - 1, 0), 63);
            int ixc = min(max(ix + dx - 1, 0), 63);
            float ry = (iyc + 0.5f) * (1.f / 32.f) - 1.f;
            float rx = (ixc + 0.5f) * (1.f / 32.f) - 1.f;
            float gy = (oy + ry + 1.f) * 31.5f;
            float gx = (ox + rx + 1.f) * 31.5f;
            g_meta[(long)j * NSLOT + g * KK + k] = make_float2(gy, gx);
        }
        __syncthreads();
    }
}

// ---------------- bilinear sampler: write xr_sel (n, 36, 512) ----------------
__global__ void sample_kernel(float* __restrict__ out)
{
    int j = blockIdx.x;
    int tid = threadIdx.x;          // 128, each does 4 channels via float4
    float* xr = out + XR_OFF;
    for (int s = 0; s < NSLOT; s++) {
        float2 m = g_meta[(long)j * NSLOT + s];
        float gy = m.x, gx = m.y;
        float y0 = floorf(gy), x0 = floorf(gx);
        float wy1 = gy - y0, wy0 = 1.f - wy1;
        float wx1 = gx - x0, wx0 = 1.f - wx1;
        float4 acc = make_float4(0.f, 0.f, 0.f, 0.f);
        #pragma unroll
        for (int t = 0; t < 4; t++) {
            float yy = y0 + (float)(t >> 1);
            float xx = x0 + (float)(t & 1);
            float w = ((t >> 1) ? wy1 : wy0) * ((t & 1) ? wx1 : wx0);
            bool ok = (yy >= 0.f) && (yy <= 63.f) && (xx >= 0.f) && (xx <= 63.f);
            if (ok && w != 0.f) {
                int yi = (int)yy, xi = (int)xx;
                const float4* row = (const float4*)(g_xT + (long)(yi * 64 + xi) * CC);
                float4 v = row[tid];
                acc.x += w * v.x; acc.y += w * v.y; acc.z += w * v.z; acc.w += w * v.w;
            }
        }
        ((float4*)(xr + ((long)j * NSLOT + s) * CC))[tid] = acc;
    }
}

// ---------------- attention: logits, softmax, xs_agg ----------------
__global__ void attn_kernel(const float* __restrict__ bk, float* __restrict__ out)
{
    __shared__ float xs_s[NSLOT * CGC];   // 18KB
    __shared__ float qk_s[4096];          // 16KB
    __shared__ float qbk_s[NH];
    __shared__ float lg[72];
    __shared__ float at[72];
    int j = blockIdx.x, tid = threadIdx.x;  // 128
    const float* xr = out + XR_OFF;

    #pragma unroll
    for (int i = 0; i < NSLOT; i++) {
        int g = i / KK;
        xs_s[i * CGC + tid] = xr[((long)j * NSLOT + i) * CC + g * CGC + tid];
    }
    #pragma unroll
    for (int i = 0; i < 32; i++)
        qk_s[i * 128 + tid] = g_qk[(long)j * 4096 + i * 128 + tid];
    if (tid < NH) {
        float s = 0.f;
        for (int d = 0; d < DH; d++)
            s += g_qsel[(long)j * CC + tid * DH + d] * bk[tid * DH + d];
        qbk_s[tid] = s;
    }
    __syncthreads();

    if (tid < 72) {
        int h = tid / KK, k = tid % KK;
        float s = 0.f;
        #pragma unroll
        for (int g = 0; g < GG; g++) {
            const float* a = &qk_s[h * CC + g * CGC];
            const float* b = &xs_s[(g * KK + k) * CGC];
            #pragma unroll 8
            for (int c = 0; c < CGC; c++) s += a[c] * b[c];
        }
        lg[tid] = (s + qbk_s[h]) * 0.125f;  // *SCALE, TAU=1
    }
    __syncthreads();

    if (tid < NH) {
        int h = tid;
        float mx = -1e30f;
        #pragma unroll
        for (int k = 0; k < KK; k++) mx = fmaxf(mx, lg[h * KK + k]);
        float e[KK], sm = 0.f;
        #pragma unroll
        for (int k = 0; k < KK; k++) { e[k] = expf(lg[h * KK + k] - mx); sm += e[k]; }
        float inv = 1.f / sm;
        #pragma unroll
        for (int k = 0; k < KK; k++) {
            float a = e[k] * inv;
            at[h * KK + k] = a;
            out[ATT_OFF + (long)h * NPT * KK + (long)j * KK + k] = a;
        }
    }
    __syncthreads();

    #pragma unroll
    for (int i = 0; i < 32; i++) {
        int o = i * 128 + tid;
        int h = o >> 9, c = o & 511, g = c >> 7, cc = c & 127;
        float s = 0.f;
        #pragma unroll
        for (int k = 0; k < KK; k++)
            s += at[h * KK + k] * xs_s[(g * KK + k) * CGC + cc];
        g_xsagg[(long)j * 4096 + o] = s;
    }
}

// ---------------- sigmoid of selected logit ----------------
__global__ void sig_kernel(const int* __restrict__ labels, float* __restrict__ out)
{
    int j = blockIdx.x * blockDim.x + threadIdx.x;
    if (j < NPT) {
        float v = out[(long)j * CC + labels[j]];
        out[SIG_OFF + j] = 1.f / (1.f + expf(-v));
    }
}

// ---------------- host ----------------
extern "C" void kernel_launch(void* const* d_in, const int* in_sizes, int n_in,
                              void* d_out, int out_size)
{
    const float* x   = (const float*)d_in[0];
    const int*   idx = (const int*)  d_in[1];
    const int*   lab = (const int*)  d_in[2];
    const float* wq  = (const float*)d_in[3];
    const float* bq  = (const float*)d_in[4];
    const float* wk  = (const float*)d_in[5];
    const float* bk  = (const float*)d_in[6];
    const float* wv  = (const float*)d_in[7];
    const float* bv  = (const float*)d_in[8];
    const float* wo  = (const float*)d_in[9];
    const float* bo  = (const float*)d_in[10];
    const float* ow1 = (const float*)d_in[11];
    const float* ob1 = (const float*)d_in[12];
    const float* g1  = (const float*)d_in[13];
    const float* b1  = (const float*)d_in[14];
    const float* ow2 = (const float*)d_in[15];
    const float* ob2 = (const float*)d_in[16];
    const float* g2  = (const float*)d_in[17];
    const float* b2  = (const float*)d_in[18];
    const float* ow3 = (const float*)d_in[19];
    float* out = (float*)d_out;

    float *xT, *qT, *t1, *t2, *qsel, *qk, *xsagg, *outT;
    cudaGetSymbolAddress((void**)&xT,    g_xT);
    cudaGetSymbolAddress((void**)&qT,    g_qT);
    cudaGetSymbolAddress((void**)&t1,    g_t1);
    cudaGetSymbolAddress((void**)&t2,    g_t2);
    cudaGetSymbolAddress((void**)&qsel,  g_qsel);
    cudaGetSymbolAddress((void**)&qk,    g_qk);
    cudaGetSymbolAddress((void**)&xsagg, g_xsagg);
    cudaGetSymbolAddress((void**)&outT,  g_outT);

    // 1) x -> xT (pixel-major)
    transpose_kernel<<<dim3(128, 16), dim3(32, 8)>>>(x);

    // 2) qT(P,C) = xT @ wq^T + bq
    sgemm_kernel<1><<<dim3(8, 32, 1), 128>>>(xT, wq, qT, bq,
        PP, CC, CC, CC, CC, CC, 0, 0, 0, 0);

    // 3) two depthwise+LN+GELU stages
    dw_ln_gelu_kernel<<<dim3(PP, GG), 128>>>(qT, t1, ow1, ob1, g1, b1,
        (long)CGC, CC);
    dw_ln_gelu_kernel<<<dim3(PP, GG), 128>>>(t1, t2, ow2, ob2, g2, b2,
        (long)PP * CGC, CGC);

    // 4) offsets -> sample coords; gather q_sel
    offset_kernel<<<NPT, 128>>>(idx, ow3);

    // 5) bilinear sampling -> xr_sel in d_out
    sample_kernel<<<NPT, 128>>>(out);

    // 6) qk(j, h*512+c) = q_sel_h @ Wk_h   (8 batched GEMMs, K=64)
    sgemm_kernel<0><<<dim3(8, 16, 8), 128>>>(qsel, wk, qk, nullptr,
        NPT, CC, DH, CC, CC, 4096, 64, (long)64 * 512, 512, 0);

    // 7) logits + softmax + attn-weighted xs aggregation
    attn_kernel<<<NPT, 128>>>(bk, out);

    // 8) outT(j, h*64+d) = xs_agg_h @ Wv_h^T + bv   (8 batched GEMMs, N=64)
    sgemm_kernel<1><<<dim3(1, 16, 8), 128>>>(xsagg, wv, outT, bv,
        NPT, DH, CC, 4096, CC, CC, 512, (long)64 * 512, 64, 64);

    // 9) y(j, c) = outT @ wo^T + bo  -> directly into d_out
    sgemm_kernel<1><<<dim3(8, 16, 1), 128>>>(outT, wo, out, bo,
        NPT, CC, CC, CC, CC, CC, 0, 0, 0, 0);

    // 10) sig = sigmoid(y[j, labels[j]])
    sig_kernel<<<8, 256>>>(lab, out);
}

// round 3
// speedup vs baseline: 1.1930x; 1.1930x over previous
#include <cuda_runtime.h>
#include <math.h>
#include <stdint.h>

// ---------------- problem constants ----------------
#define HH 64
#define WW 64
#define PP 4096          // H*W
#define CC 512
#define CGC 128
#define GG 4
#define KK 9
#define NH 8
#define DH 64
#define NPT 2048         // n selected points
#define NSLOT 36         // G*K

// d_out layout: y (2048*512) | attn (8*2048*9) | xr_sel (2048*36*512) | sig (2048)
#define Y_OFF   0L
#define ATT_OFF 1048576L
#define XR_OFF  1196032L
#define SIG_OFF 38944768L

// ---------------- scratch (device globals; no runtime alloc) ----------------
__device__ float  g_xT  [(long)PP * CC];       // x transposed: (pixel, channel)
__device__ float  g_qT  [(long)PP * CC];       // q: (pixel, channel)
__device__ float  g_t1  [(long)GG * PP * CGC]; // (g, pixel, cc)
__device__ float  g_t2  [(long)GG * PP * CGC];
__device__ float2 g_meta[(long)NPT * NSLOT];   // (gy, gx) per (j, g*9+k)
__device__ float  g_qsel[(long)NPT * CC];      // q at selected points (j, c)
__device__ float  g_qk  [(long)NPT * 4096];    // (j, h*512+c)
__device__ float  g_xsagg[(long)NPT * 4096];   // (j, h*512+c)
__device__ float  g_outT[(long)NPT * CC];      // (j, h*64+d)

// ---------------- mma.sync tf32 helpers ----------------
__device__ __forceinline__ uint32_t tf32r(float f) {
    uint32_t u; asm("cvt.rna.tf32.f32 %0, %1;" : "=r"(u) : "f"(f)); return u;
}
__device__ __forceinline__ void split_hl(float v, float& h, float& l) {
    float hf = __uint_as_float(tf32r(v));
    h = hf;
    l = __uint_as_float(tf32r(v - hf));
}
__device__ __forceinline__ void mma8(float* c, const uint32_t* a, const uint32_t* b) {
    asm volatile("mma.sync.aligned.m16n8k8.row.col.f32.tf32.tf32.f32 "
        "{%0,%1,%2,%3}, {%4,%5,%6,%7}, {%8,%9}, {%0,%1,%2,%3};"
        : "+f"(c[0]), "+f"(c[1]), "+f"(c[2]), "+f"(c[3])
        : "r"(a[0]), "r"(a[1]), "r"(a[2]), "r"(a[3]), "r"(b[0]), "r"(b[1]));
}

// ================= 3xTF32 mma.sync GEMM (~fp32 accuracy) =================
// C(M,N) = A(M,K) * B + bias.  TB=1: B[n][k] = Bg[n*ldb+k].  TB=0: B[k][n] = Bg[k*ldb+n].
// BM=128, BN=64, BK=16. 128 threads = 4 warps (2m x 2n), warp tile 64x32.
template<int TB>
__global__ __launch_bounds__(128) void gemm_mma_kernel(
    const float* __restrict__ A, const float* __restrict__ B,
    float* __restrict__ C, const float* __restrict__ bias,
    int M, int N, int Kd, int lda, int ldb, int ldc,
    long aOff, long bOff, long cOff, long biasOff)
{
    const int BM = 128, BN = 64, BK = 16;
    __shared__ float Ah[BK][BM + 4], Al[BK][BM + 4];
    __shared__ float Bh[BK][BN + 4], Bl[BK][BN + 4];

    int z = blockIdx.z;
    A += (long)z * aOff; B += (long)z * bOff; C += (long)z * cOff;
    if (bias) bias += (long)z * biasOff;

    int m0 = blockIdx.y * BM, n0 = blockIdx.x * BN;
    int tid = threadIdx.x, wid = tid >> 5, lane = tid & 31;
    int wm = (wid >> 1) * 64, wn = (wid & 1) * 32;
    int g = lane >> 2, tig = lane & 3;

    float acc[4][4][4];
    #pragma unroll
    for (int mi = 0; mi < 4; mi++)
        #pragma unroll
        for (int ni = 0; ni < 4; ni++)
            #pragma unroll
            for (int c = 0; c < 4; c++) acc[mi][ni][c] = 0.f;

    for (int k0 = 0; k0 < Kd; k0 += BK) {
        // ---- load A tile: 128 x 16, K-contiguous ----
        #pragma unroll
        for (int i = 0; i < 4; i++) {
            int e = tid + i * 128;
            int m = e >> 2, k4 = (e & 3) * 4;
            float4 v = *(const float4*)(A + (long)(m0 + m) * lda + k0 + k4);
            split_hl(v.x, Ah[k4 + 0][m], Al[k4 + 0][m]);
            split_hl(v.y, Ah[k4 + 1][m], Al[k4 + 1][m]);
            split_hl(v.z, Ah[k4 + 2][m], Al[k4 + 2][m]);
            split_hl(v.w, Ah[k4 + 3][m], Al[k4 + 3][m]);
        }
        // ---- load B tile: 64 x 16 ----
        if (TB) {
            #pragma unroll
            for (int i = 0; i < 2; i++) {
                int e = tid + i * 128;
                int n = e >> 2, k4 = (e & 3) * 4;
                float4 v = *(const float4*)(B + (long)(n0 + n) * ldb + k0 + k4);
                split_hl(v.x, Bh[k4 + 0][n], Bl[k4 + 0][n]);
                split_hl(v.y, Bh[k4 + 1][n], Bl[k4 + 1][n]);
                split_hl(v.z, Bh[k4 + 2][n], Bl[k4 + 2][n]);
                split_hl(v.w, Bh[k4 + 3][n], Bl[k4 + 3][n]);
            }
        } else {
            #pragma unroll
            for (int i = 0; i < 2; i++) {
                int e = tid + i * 128;
                int k = e >> 4, n4 = (e & 15) * 4;
                float4 v = *(const float4*)(B + (long)(k0 + k) * ldb + n0 + n4);
                float4 h, l;
                split_hl(v.x, h.x, l.x); split_hl(v.y, h.y, l.y);
                split_hl(v.z, h.z, l.z); split_hl(v.w, h.w, l.w);
                *(float4*)&Bh[k][n4] = h;
                *(float4*)&Bl[k][n4] = l;
            }
        }
        __syncthreads();

        #pragma unroll
        for (int ks = 0; ks < BK; ks += 8) {
            uint32_t ahf[4][4], alf[4][4], bhf[4][2], blf[4][2];
            #pragma unroll
            for (int mi = 0; mi < 4; mi++) {
                int mr = wm + mi * 16 + g;
                ahf[mi][0] = __float_as_uint(Ah[ks + tig][mr]);
                ahf[mi][1] = __float_as_uint(Ah[ks + tig][mr + 8]);
                ahf[mi][2] = __float_as_uint(Ah[ks + tig + 4][mr]);
                ahf[mi][3] = __float_as_uint(Ah[ks + tig + 4][mr + 8]);
                alf[mi][0] = __float_as_uint(Al[ks + tig][mr]);
                alf[mi][1] = __float_as_uint(Al[ks + tig][mr + 8]);
                alf[mi][2] = __float_as_uint(Al[ks + tig + 4][mr]);
                alf[mi][3] = __float_as_uint(Al[ks + tig + 4][mr + 8]);
            }
            #pragma unroll
            for (int ni = 0; ni < 4; ni++) {
                int nr = wn + ni * 8 + g;
                bhf[ni][0] = __float_as_uint(Bh[ks + tig][nr]);
                bhf[ni][1] = __float_as_uint(Bh[ks + tig + 4][nr]);
                blf[ni][0] = __float_as_uint(Bl[ks + tig][nr]);
                blf[ni][1] = __float_as_uint(Bl[ks + tig + 4][nr]);
            }
            #pragma unroll
            for (int mi = 0; mi < 4; mi++)
                #pragma unroll
                for (int ni = 0; ni < 4; ni++) {
                    mma8(acc[mi][ni], ahf[mi], bhf[ni]);
                    mma8(acc[mi][ni], ahf[mi], blf[ni]);
                    mma8(acc[mi][ni], alf[mi], bhf[ni]);
                }
        }
        __syncthreads();
    }

    // ---- epilogue ----
    #pragma unroll
    for (int ni = 0; ni < 4; ni++) {
        int col = n0 + wn + ni * 8 + 2 * tig;
        float b0 = 0.f, b1 = 0.f;
        if (bias) { b0 = bias[col]; b1 = bias[col + 1]; }
        #pragma unroll
        for (int mi = 0; mi < 4; mi++) {
            int row = m0 + wm + mi * 16 + g;
            float2 v0 = make_float2(acc[mi][ni][0] + b0, acc[mi][ni][1] + b1);
            float2 v1 = make_float2(acc[mi][ni][2] + b0, acc[mi][ni][3] + b1);
            *(float2*)(C + (long)row * ldc + col) = v0;
            *(float2*)(C + (long)(row + 8) * ldc + col) = v1;
        }
    }
}

// ---------------- transpose x (C,P) -> xT (P,C) ----------------
__global__ void transpose_kernel(const float* __restrict__ x)
{
    __shared__ float tile[32][33];
    int pb = blockIdx.x * 32;
    int cb = blockIdx.y * 32;
    int tx = threadIdx.x, ty = threadIdx.y;
    #pragma unroll
    for (int i = 0; i < 32; i += 8)
        tile[ty + i][tx] = x[(long)(cb + ty + i) * PP + pb + tx];
    __syncthreads();
    #pragma unroll
    for (int i = 0; i < 32; i += 8)
        g_xT[(long)(pb + ty + i) * CC + cb + tx] = tile[tx][ty + i];
}

// ---------------- depthwise3x3 + LayerNorm(channels) + GELU ----------------
__global__ void dw_ln_gelu_kernel(const float* __restrict__ in, float* __restrict__ outp,
                                  const float* __restrict__ w, const float* __restrict__ cb,
                                  const float* __restrict__ gamma, const float* __restrict__ beta,
                                  long gStride, int pixStride)
{
    int p = blockIdx.x;
    int g = blockIdx.y;
    int cc = threadIdx.x;           // 128
    int h = p >> 6, wx = p & 63;
    const float* base = in + (long)g * gStride + cc;

    float acc = cb[cc];
    #pragma unroll
    for (int dy = 0; dy < 3; dy++) {
        int yy = h + dy - 1;
        if ((unsigned)yy < 64u) {
            #pragma unroll
            for (int dx = 0; dx < 3; dx++) {
                int xx = wx + dx - 1;
                if ((unsigned)xx < 64u)
                    acc += base[(long)(yy * 64 + xx) * pixStride] * w[cc * 9 + dy * 3 + dx];
            }
        }
    }
    float s1 = acc, s2 = acc * acc;
    #pragma unroll
    for (int o = 16; o > 0; o >>= 1) {
        s1 += __shfl_xor_sync(0xffffffffu, s1, o);
        s2 += __shfl_xor_sync(0xffffffffu, s2, o);
    }
    __shared__ float r1[4], r2[4];
    int warp = cc >> 5, lane = cc & 31;
    if (lane == 0) { r1[warp] = s1; r2[warp] = s2; }
    __syncthreads();
    float t1s = r1[0] + r1[1] + r1[2] + r1[3];
    float t2s = r2[0] + r2[1] + r2[2] + r2[3];
    float mean = t1s * (1.f / 128.f);
    float var  = fmaxf(t2s * (1.f / 128.f) - mean * mean, 0.f);
    float nv = (acc - mean) * rsqrtf(var + 1e-5f) * gamma[cc] + beta[cc];
    float ge = 0.5f * nv * (1.f + erff(nv * 0.70710678118654752f));
    outp[((long)g * PP + p) * CGC + cc] = ge;
}

// ---------------- offsets + sample coords at selected points; gather q_sel ----------------
__global__ void offset_kernel(const int* __restrict__ idx, const float* __restrict__ ow3)
{
    int j = blockIdx.x;
    int tid = threadIdx.x;          // 128
    __shared__ float tv[128];
    __shared__ float offv[18];
    int iy = idx[2 * j], ix = idx[2 * j + 1];
    int p = iy * 64 + ix;

    const float4* qrow = (const float4*)(g_qT + (long)p * CC);
    float4* qs = (float4*)(g_qsel + (long)j * CC);
    qs[tid] = qrow[tid];

    for (int g = 0; g < GG; g++) {
        tv[tid] = g_t2[((long)g * PP + p) * CGC + tid];
        __syncthreads();
        if (tid < 18) {
            float s = 0.f;
            #pragma unroll 8
            for (int c = 0; c < 128; c++) s += tv[c] * ow3[tid * 128 + c];
            offv[tid] = s;
        }
        __syncthreads();
        if (tid < KK) {
            int k = tid, dy = k / 3, dx = k % 3;
            float oy = tanhf(offv[2 * k])     * (1.f / 32.f);
            float ox = tanhf(offv[2 * k + 1]) * (1.f / 32.f);
            int iyc = min(max(iy + dy - 1, 0), 63);
            int ixc = min(max(ix + dx - 1, 0), 63);
            float ry = (iyc + 0.5f) * (1.f / 32.f) - 1.f;
            float rx = (ixc + 0.5f) * (1.f / 32.f) - 1.f;
            float gy = (oy + ry + 1.f) * 31.5f;
            float gx = (ox + rx + 1.f) * 31.5f;
            g_meta[(long)j * NSLOT + g * KK + k] = make_float2(gy, gx);
        }
        __syncthreads();
    }
}

// ---------------- bilinear sampler: write xr_sel (n, 36, 512) ----------------
__global__ void sample_kernel(float* __restrict__ out)
{
    int j = blockIdx.x;
    int tid = threadIdx.x;          // 128, each does 4 channels via float4
    float* xr = out + XR_OFF;
    for (int s = 0; s < NSLOT; s++) {
        float2 m = g_meta[(long)j * NSLOT + s];
        float gy = m.x, gx = m.y;
        float y0 = floorf(gy), x0 = floorf(gx);
        float wy1 = gy - y0, wy0 = 1.f - wy1;
        float wx1 = gx - x0, wx0 = 1.f - wx1;
        float4 acc = make_float4(0.f, 0.f, 0.f, 0.f);
        #pragma unroll
        for (int t = 0; t < 4; t++) {
            float yy = y0 + (float)(t >> 1);
            float xx = x0 + (float)(t & 1);
            float w = ((t >> 1) ? wy1 : wy0) * ((t & 1) ? wx1 : wx0);
            bool ok = (yy >= 0.f) && (yy <= 63.f) && (xx >= 0.f) && (xx <= 63.f);
            if (ok && w != 0.f) {
                int yi = (int)yy, xi = (int)xx;
                const float4* row = (const float4*)(g_xT + (long)(yi * 64 + xi) * CC);
                float4 v = row[tid];
                acc.x += w * v.x; acc.y += w * v.y; acc.z += w * v.z; acc.w += w * v.w;
            }
        }
        ((float4*)(xr + ((long)j * NSLOT + s) * CC))[tid] = acc;
    }
}

// ---------------- attention: logits, softmax, xs_agg ----------------
__global__ void attn_kernel(const float* __restrict__ bk, float* __restrict__ out)
{
    __shared__ float xs_s[NSLOT * CGC];
    __shared__ float qk_s[4096];
    __shared__ float qbk_s[NH];
    __shared__ float lg[72];
    __shared__ float at[72];
    int j = blockIdx.x, tid = threadIdx.x;  // 128
    const float* xr = out + XR_OFF;

    #pragma unroll
    for (int i = 0; i < NSLOT; i++) {
        int g = i / KK;
        xs_s[i * CGC + tid] = xr[((long)j * NSLOT + i) * CC + g * CGC + tid];
    }
    #pragma unroll
    for (int i = 0; i < 32; i++)
        qk_s[i * 128 + tid] = g_qk[(long)j * 4096 + i * 128 + tid];
    if (tid < NH) {
        float s = 0.f;
        for (int d = 0; d < DH; d++)
            s += g_qsel[(long)j * CC + tid * DH + d] * bk[tid * DH + d];
        qbk_s[tid] = s;
    }
    __syncthreads();

    if (tid < 72) {
        int h = tid / KK, k = tid % KK;
        float s = 0.f;
        #pragma unroll
        for (int g = 0; g < GG; g++) {
            const float* a = &qk_s[h * CC + g * CGC];
            const float* b = &xs_s[(g * KK + k) * CGC];
            #pragma unroll 8
            for (int c = 0; c < CGC; c++) s += a[c] * b[c];
        }
        lg[tid] = (s + qbk_s[h]) * 0.125f;
    }
    __syncthreads();

    if (tid < NH) {
        int h = tid;
        float mx = -1e30f;
        #pragma unroll
        for (int k = 0; k < KK; k++) mx = fmaxf(mx, lg[h * KK + k]);
        float e[KK], sm = 0.f;
        #pragma unroll
        for (int k = 0; k < KK; k++) { e[k] = expf(lg[h * KK + k] - mx); sm += e[k]; }
        float inv = 1.f / sm;
        #pragma unroll
        for (int k = 0; k < KK; k++) {
            float a = e[k] * inv;
            at[h * KK + k] = a;
            out[ATT_OFF + (long)h * NPT * KK + (long)j * KK + k] = a;
        }
    }
    __syncthreads();

    #pragma unroll
    for (int i = 0; i < 32; i++) {
        int o = i * 128 + tid;
        int h = o >> 9, c = o & 511, g = c >> 7, cc = c & 127;
        float s = 0.f;
        #pragma unroll
        for (int k = 0; k < KK; k++)
            s += at[h * KK + k] * xs_s[(g * KK + k) * CGC + cc];
        g_xsagg[(long)j * 4096 + o] = s;
    }
}

// ---------------- sigmoid of selected logit ----------------
__global__ void sig_kernel(const int* __restrict__ labels, float* __restrict__ out)
{
    int j = blockIdx.x * blockDim.x + threadIdx.x;
    if (j < NPT) {
        float v = out[(long)j * CC + labels[j]];
        out[SIG_OFF + j] = 1.f / (1.f + expf(-v));
    }
}

// ---------------- host ----------------
extern "C" void kernel_launch(void* const* d_in, const int* in_sizes, int n_in,
                              void* d_out, int out_size)
{
    const float* x   = (const float*)d_in[0];
    const int*   idx = (const int*)  d_in[1];
    const int*   lab = (const int*)  d_in[2];
    const float* wq  = (const float*)d_in[3];
    const float* bq  = (const float*)d_in[4];
    const float* wk  = (const float*)d_in[5];
    const float* bk  = (const float*)d_in[6];
    const float* wv  = (const float*)d_in[7];
    const float* bv  = (const float*)d_in[8];
    const float* wo  = (const float*)d_in[9];
    const float* bo  = (const float*)d_in[10];
    const float* ow1 = (const float*)d_in[11];
    const float* ob1 = (const float*)d_in[12];
    const float* g1  = (const float*)d_in[13];
    const float* b1  = (const float*)d_in[14];
    const float* ow2 = (const float*)d_in[15];
    const float* ob2 = (const float*)d_in[16];
    const float* g2  = (const float*)d_in[17];
    const float* b2  = (const float*)d_in[18];
    const float* ow3 = (const float*)d_in[19];
    float* out = (float*)d_out;

    float *xT, *qT, *t1, *t2, *qsel, *qk, *xsagg, *outT;
    cudaGetSymbolAddress((void**)&xT,    g_xT);
    cudaGetSymbolAddress((void**)&qT,    g_qT);
    cudaGetSymbolAddress((void**)&t1,    g_t1);
    cudaGetSymbolAddress((void**)&t2,    g_t2);
    cudaGetSymbolAddress((void**)&qsel,  g_qsel);
    cudaGetSymbolAddress((void**)&qk,    g_qk);
    cudaGetSymbolAddress((void**)&xsagg, g_xsagg);
    cudaGetSymbolAddress((void**)&outT,  g_outT);

    // 1) x -> xT (pixel-major)
    transpose_kernel<<<dim3(128, 16), dim3(32, 8)>>>(x);

    // 2) qT(P,C) = xT @ wq^T + bq
    gemm_mma_kernel<1><<<dim3(8, 32, 1), 128>>>(xT, wq, qT, bq,
        PP, CC, CC, CC, CC, CC, 0, 0, 0, 0);

    // 3) two depthwise+LN+GELU stages
    dw_ln_gelu_kernel<<<dim3(PP, GG), 128>>>(qT, t1, ow1, ob1, g1, b1,
        (long)CGC, CC);
    dw_ln_gelu_kernel<<<dim3(PP, GG), 128>>>(t1, t2, ow2, ob2, g2, b2,
        (long)PP * CGC, CGC);

    // 4) offsets -> sample coords; gather q_sel
    offset_kernel<<<NPT, 128>>>(idx, ow3);

    // 5) bilinear sampling -> xr_sel in d_out
    sample_kernel<<<NPT, 128>>>(out);

    // 6) qk(j, h*512+c) = q_sel_h @ Wk_h   (8 batched, K=64, B is [K,N] layout)
    gemm_mma_kernel<0><<<dim3(8, 16, 8), 128>>>(qsel, wk, qk, nullptr,
        NPT, CC, DH, CC, CC, 4096, 64, (long)64 * 512, 512, 0);

    // 7) logits + softmax + attn-weighted xs aggregation
    attn_kernel<<<NPT, 128>>>(bk, out);

    // 8) outT(j, h*64+d) = xs_agg_h @ Wv_h^T + bv   (8 batched, N=64)
    gemm_mma_kernel<1><<<dim3(1, 16, 8), 128>>>(xsagg, wv, outT, bv,
        NPT, DH, CC, 4096, CC, CC, 512, (long)64 * 512, 64, 64);

    // 9) y(j, c) = outT @ wo^T + bo  -> directly into d_out
    gemm_mma_kernel<1><<<dim3(8, 16, 1), 128>>>(outT, wo, out, bo,
        NPT, CC, CC, CC, CC, CC, 0, 0, 0, 0);

    // 10) sig = sigmoid(y[j, labels[j]])
    sig_kernel<<<8, 256>>>(lab, out);
}

// round 4
// speedup vs baseline: 1.2768x; 1.0702x over previous
#include <cuda_runtime.h>
#include <cuda_bf16.h>
#include <math.h>
#include <stdint.h>

// ---------------- problem constants ----------------
#define HH 64
#define WW 64
#define PP 4096          // H*W
#define CC 512
#define CGC 128
#define GG 4
#define KK 9
#define NH 8
#define DH 64
#define NPT 2048         // n selected points
#define NSLOT 36         // G*K

// d_out layout: y (2048*512) | attn (8*2048*9) | xr_sel (2048*36*512) | sig (2048)
#define Y_OFF   0L
#define ATT_OFF 1048576L
#define XR_OFF  1196032L
#define SIG_OFF 38944768L

// ---------------- scratch (device globals; no runtime alloc) ----------------
__device__ float  g_xT  [(long)PP * CC];       // x transposed: (pixel, channel)
__device__ float  g_qT  [(long)PP * CC];       // q: (pixel, channel)
__device__ float  g_t1  [(long)GG * PP * CGC]; // (g, pixel, cc)
__device__ float  g_t2  [(long)GG * PP * CGC];
__device__ float2 g_meta[(long)NPT * NSLOT];   // (gy, gx) per (j, g*9+k)
__device__ float  g_qsel[(long)NPT * CC];      // q at selected points (j, c)
__device__ float  g_qk  [(long)NPT * 4096];    // (j, h*512+c)
__device__ float  g_xsagg[(long)NPT * 4096];   // (j, h*512+c)
__device__ float  g_outT[(long)NPT * CC];      // (j, h*64+d)

// ---------------- bf16 split helpers ----------------
// pack (v0 -> low half, v1 -> high half) as bf16x2; return hi word, lo (residual) word
__device__ __forceinline__ void split2(float v0, float v1, uint32_t& h, uint32_t& l) {
    uint32_t hw;
    asm("cvt.rn.bf16x2.f32 %0, %1, %2;" : "=r"(hw) : "f"(v1), "f"(v0));
    float f0 = __uint_as_float(hw << 16);
    float f1 = __uint_as_float(hw & 0xffff0000u);
    uint32_t lw;
    asm("cvt.rn.bf16x2.f32 %0, %1, %2;" : "=r"(lw) : "f"(v1 - f1), "f"(v0 - f0));
    h = hw; l = lw;
}
__device__ __forceinline__ void split1(float v, uint16_t& h, uint16_t& l) {
    __nv_bfloat16 hb = __float2bfloat16_rn(v);
    float hf = __bfloat162float(hb);
    __nv_bfloat16 lb = __float2bfloat16_rn(v - hf);
    h = __bfloat16_as_ushort(hb);
    l = __bfloat16_as_ushort(lb);
}
__device__ __forceinline__ void mma16(float* c, const uint32_t* a, const uint32_t* b) {
    asm volatile("mma.sync.aligned.m16n8k16.row.col.f32.bf16.bf16.f32 "
        "{%0,%1,%2,%3}, {%4,%5,%6,%7}, {%8,%9}, {%0,%1,%2,%3};"
        : "+f"(c[0]), "+f"(c[1]), "+f"(c[2]), "+f"(c[3])
        : "r"(a[0]), "r"(a[1]), "r"(a[2]), "r"(a[3]), "r"(b[0]), "r"(b[1]));
}

// ================= 3-term split-bf16 mma.sync GEMM (~fp32 accuracy) =================
// C(M,N) = A(M,K) * B + bias.  TB=1: B[n][k] = Bg[n*ldb+k].  TB=0: B[k][n] = Bg[k*ldb+n].
// BM=128, BN=64, BK=16. 128 threads = 4 warps (2m x 2n), warp tile 64x32.
// smem rows: 8 bf16x2 words padded to stride 12 (conflict-free fragment LDS).
template<int TB>
__global__ __launch_bounds__(128) void gemm_mma_kernel(
    const float* __restrict__ A, const float* __restrict__ B,
    float* __restrict__ C, const float* __restrict__ bias,
    int M, int N, int Kd, int lda, int ldb, int ldc,
    long aOff, long bOff, long cOff, long biasOff)
{
    const int BM = 128, BN = 64, BK = 16;
    __shared__ __align__(16) uint32_t Ah[BM * 12], Al[BM * 12];
    __shared__ __align__(16) uint32_t Bh[BN * 12], Bl[BN * 12];

    int z = blockIdx.z;
    A += (long)z * aOff; B += (long)z * bOff; C += (long)z * cOff;
    if (bias) bias += (long)z * biasOff;

    int m0 = blockIdx.y * BM, n0 = blockIdx.x * BN;
    int tid = threadIdx.x, wid = tid >> 5, lane = tid & 31;
    int wm = (wid >> 1) * 64, wn = (wid & 1) * 32;
    int g = lane >> 2, tig = lane & 3;

    float acc[4][4][4];
    #pragma unroll
    for (int mi = 0; mi < 4; mi++)
        #pragma unroll
        for (int ni = 0; ni < 4; ni++)
            #pragma unroll
            for (int c = 0; c < 4; c++) acc[mi][ni][c] = 0.f;

    for (int k0 = 0; k0 < Kd; k0 += BK) {
        // ---- A tile: row m = tid, 16 floats K-contiguous -> 8 hi + 8 lo words ----
        {
            const float* ap = A + (long)(m0 + tid) * lda + k0;
            uint4 h0, h1, l0, l1;
            float4 v;
            v = *(const float4*)(ap);
            split2(v.x, v.y, h0.x, l0.x); split2(v.z, v.w, h0.y, l0.y);
            v = *(const float4*)(ap + 4);
            split2(v.x, v.y, h0.z, l0.z); split2(v.z, v.w, h0.w, l0.w);
            v = *(const float4*)(ap + 8);
            split2(v.x, v.y, h1.x, l1.x); split2(v.z, v.w, h1.y, l1.y);
            v = *(const float4*)(ap + 12);
            split2(v.x, v.y, h1.z, l1.z); split2(v.z, v.w, h1.w, l1.w);
            *(uint4*)&Ah[tid * 12]     = h0;
            *(uint4*)&Ah[tid * 12 + 4] = h1;
            *(uint4*)&Al[tid * 12]     = l0;
            *(uint4*)&Al[tid * 12 + 4] = l1;
        }
        // ---- B tile: 64 rows x 16 ----
        if (TB) {
            int n  = tid >> 1;
            int hf = (tid & 1) * 8;
            const float* bp = B + (long)(n0 + n) * ldb + k0 + hf;
            uint4 h, l;
            float4 v;
            v = *(const float4*)(bp);
            split2(v.x, v.y, h.x, l.x); split2(v.z, v.w, h.y, l.y);
            v = *(const float4*)(bp + 4);
            split2(v.x, v.y, h.z, l.z); split2(v.z, v.w, h.w, l.w);
            *(uint4*)&Bh[n * 12 + hf / 2] = h;
            *(uint4*)&Bl[n * 12 + hf / 2] = l;
        } else {
            uint16_t* bh16 = (uint16_t*)Bh;
            uint16_t* bl16 = (uint16_t*)Bl;
            #pragma unroll
            for (int i = 0; i < 2; i++) {
                int e = tid + i * 128;
                int k = e >> 4, n4 = (e & 15) * 4;
                float4 v = *(const float4*)(B + (long)(k0 + k) * ldb + n0 + n4);
                uint16_t h, l;
                split1(v.x, h, l); bh16[(n4 + 0) * 24 + k] = h; bl16[(n4 + 0) * 24 + k] = l;
                split1(v.y, h, l); bh16[(n4 + 1) * 24 + k] = h; bl16[(n4 + 1) * 24 + k] = l;
                split1(v.z, h, l); bh16[(n4 + 2) * 24 + k] = h; bl16[(n4 + 2) * 24 + k] = l;
                split1(v.w, h, l); bh16[(n4 + 3) * 24 + k] = h; bl16[(n4 + 3) * 24 + k] = l;
            }
        }
        __syncthreads();

        uint32_t ahf[4][4], alf[4][4], bhf[4][2], blf[4][2];
        #pragma unroll
        for (int mi = 0; mi < 4; mi++) {
            int mr = wm + mi * 16 + g;
            ahf[mi][0] = Ah[mr * 12 + tig];
            ahf[mi][1] = Ah[(mr + 8) * 12 + tig];
            ahf[mi][2] = Ah[mr * 12 + tig + 4];
            ahf[mi][3] = Ah[(mr + 8) * 12 + tig + 4];
            alf[mi][0] = Al[mr * 12 + tig];
            alf[mi][1] = Al[(mr + 8) * 12 + tig];
            alf[mi][2] = Al[mr * 12 + tig + 4];
            alf[mi][3] = Al[(mr + 8) * 12 + tig + 4];
        }
        #pragma unroll
        for (int ni = 0; ni < 4; ni++) {
            int nr = wn + ni * 8 + g;
            bhf[ni][0] = Bh[nr * 12 + tig];
            bhf[ni][1] = Bh[nr * 12 + tig + 4];
            blf[ni][0] = Bl[nr * 12 + tig];
            blf[ni][1] = Bl[nr * 12 + tig + 4];
        }
        #pragma unroll
        for (int mi = 0; mi < 4; mi++)
            #pragma unroll
            for (int ni = 0; ni < 4; ni++) {
                mma16(acc[mi][ni], ahf[mi], bhf[ni]);
                mma16(acc[mi][ni], ahf[mi], blf[ni]);
                mma16(acc[mi][ni], alf[mi], bhf[ni]);
            }
        __syncthreads();
    }

    // ---- epilogue ----
    #pragma unroll
    for (int ni = 0; ni < 4; ni++) {
        int col = n0 + wn + ni * 8 + 2 * tig;
        float b0 = 0.f, b1 = 0.f;
        if (bias) { b0 = bias[col]; b1 = bias[col + 1]; }
        #pragma unroll
        for (int mi = 0; mi < 4; mi++) {
            int row = m0 + wm + mi * 16 + g;
            float2 v0 = make_float2(acc[mi][ni][0] + b0, acc[mi][ni][1] + b1);
            float2 v1 = make_float2(acc[mi][ni][2] + b0, acc[mi][ni][3] + b1);
            *(float2*)(C + (long)row * ldc + col) = v0;
            *(float2*)(C + (long)(row + 8) * ldc + col) = v1;
        }
    }
}

// ---------------- transpose x (C,P) -> xT (P,C) ----------------
__global__ void transpose_kernel(const float* __restrict__ x)
{
    __shared__ float tile[32][33];
    int pb = blockIdx.x * 32;
    int cb = blockIdx.y * 32;
    int tx = threadIdx.x, ty = threadIdx.y;
    #pragma unroll
    for (int i = 0; i < 32; i += 8)
        tile[ty + i][tx] = x[(long)(cb + ty + i) * PP + pb + tx];
    __syncthreads();
    #pragma unroll
    for (int i = 0; i < 32; i += 8)
        g_xT[(long)(pb + ty + i) * CC + cb + tx] = tile[tx][ty + i];
}

// ---------------- depthwise3x3 + LayerNorm(channels) + GELU ----------------
__global__ void dw_ln_gelu_kernel(const float* __restrict__ in, float* __restrict__ outp,
                                  const float* __restrict__ w, const float* __restrict__ cb,
                                  const float* __restrict__ gamma, const float* __restrict__ beta,
                                  long gStride, int pixStride)
{
    int p = blockIdx.x;
    int g = blockIdx.y;
    int cc = threadIdx.x;           // 128
    int h = p >> 6, wx = p & 63;
    const float* base = in + (long)g * gStride + cc;

    float acc = cb[cc];
    #pragma unroll
    for (int dy = 0; dy < 3; dy++) {
        int yy = h + dy - 1;
        if ((unsigned)yy < 64u) {
            #pragma unroll
            for (int dx = 0; dx < 3; dx++) {
                int xx = wx + dx - 1;
                if ((unsigned)xx < 64u)
                    acc += base[(long)(yy * 64 + xx) * pixStride] * w[cc * 9 + dy * 3 + dx];
            }
        }
    }
    float s1 = acc, s2 = acc * acc;
    #pragma unroll
    for (int o = 16; o > 0; o >>= 1) {
        s1 += __shfl_xor_sync(0xffffffffu, s1, o);
        s2 += __shfl_xor_sync(0xffffffffu, s2, o);
    }
    __shared__ float r1[4], r2[4];
    int warp = cc >> 5, lane = cc & 31;
    if (lane == 0) { r1[warp] = s1; r2[warp] = s2; }
    __syncthreads();
    float t1s = r1[0] + r1[1] + r1[2] + r1[3];
    float t2s = r2[0] + r2[1] + r2[2] + r2[3];
    float mean = t1s * (1.f / 128.f);
    float var  = fmaxf(t2s * (1.f / 128.f) - mean * mean, 0.f);
    float nv = (acc - mean) * rsqrtf(var + 1e-5f) * gamma[cc] + beta[cc];
    float ge = 0.5f * nv * (1.f + erff(nv * 0.70710678118654752f));
    outp[((long)g * PP + p) * CGC + cc] = ge;
}

// ---------------- offsets + sample coords at selected points; gather q_sel ----------------
__global__ void offset_kernel(const int* __restrict__ idx, const float* __restrict__ ow3)
{
    int j = blockIdx.x;
    int tid = threadIdx.x;          // 128
    __shared__ float tv[128];
    __shared__ float offv[18];
    int iy = idx[2 * j], ix = idx[2 * j + 1];
    int p = iy * 64 + ix;

    const float4* qrow = (const float4*)(g_qT + (long)p * CC);
    float4* qs = (float4*)(g_qsel + (long)j * CC);
    qs[tid] = qrow[tid];

    for (int g = 0; g < GG; g++) {
        tv[tid] = g_t2[((long)g * PP + p) * CGC + tid];
        __syncthreads();
        if (tid < 18) {
            float s = 0.f;
            #pragma unroll 8
            for (int c = 0; c < 128; c++) s += tv[c] * ow3[tid * 128 + c];
            offv[tid] = s;
        }
        __syncthreads();
        if (tid < KK) {
            int k = tid, dy = k / 3, dx = k % 3;
            float oy = tanhf(offv[2 * k])     * (1.f / 32.f);
            float ox = tanhf(offv[2 * k + 1]) * (1.f / 32.f);
            int iyc = min(max(iy + dy - 1, 0), 63);
            int ixc = min(max(ix + dx - 1, 0), 63);
            float ry = (iyc + 0.5f) * (1.f / 32.f) - 1.f;
            float rx = (ixc + 0.5f) * (1.f / 32.f) - 1.f;
            float gy = (oy + ry + 1.f) * 31.5f;
            float gx = (ox + rx + 1.f) * 31.5f;
            g_meta[(long)j * NSLOT + g * KK + k] = make_float2(gy, gx);
        }
        __syncthreads();
    }
}

// ---------------- fused bilinear sampler + attention ----------------
// Samples all 36 slots x 512 channels, writes xr_sel, keeps the group-diagonal
// slice in smem, then computes logits, softmax (-> attn out), and xs aggregation.
__global__ __launch_bounds__(128) void sample_attn_kernel(
    const float* __restrict__ bk, float* __restrict__ out)
{
    __shared__ float xs_s[NSLOT * CGC];   // 18KB: diagonal slice
    __shared__ float qk_s[4096];          // 16KB
    __shared__ float qbk_s[NH];
    __shared__ float lg[72];
    __shared__ float at[72];
    int j = blockIdx.x, tid = threadIdx.x;  // 128
    float* xr = out + XR_OFF;
    int myg = tid >> 5;                   // group owned by this thread's channels

    #pragma unroll
    for (int i = 0; i < 32; i++)
        qk_s[i * 128 + tid] = g_qk[(long)j * 4096 + i * 128 + tid];
    if (tid < NH) {
        float s = 0.f;
        for (int d = 0; d < DH; d++)
            s += g_qsel[(long)j * CC + tid * DH + d] * bk[tid * DH + d];
        qbk_s[tid] = s;
    }

    for (int s = 0; s < NSLOT; s++) {
        float2 m = g_meta[(long)j * NSLOT + s];
        float gy = m.x, gx = m.y;
        float y0 = floorf(gy), x0 = floorf(gx);
        float wy1 = gy - y0, wy0 = 1.f - wy1;
        float wx1 = gx - x0, wx0 = 1.f - wx1;
        float4 acc = make_float4(0.f, 0.f, 0.f, 0.f);
        #pragma unroll
        for (int t = 0; t < 4; t++) {
            float yy = y0 + (float)(t >> 1);
            float xx = x0 + (float)(t & 1);
            float w = ((t >> 1) ? wy1 : wy0) * ((t & 1) ? wx1 : wx0);
            bool ok = (yy >= 0.f) && (yy <= 63.f) && (xx >= 0.f) && (xx <= 63.f);
            if (ok && w != 0.f) {
                int yi = (int)yy, xi = (int)xx;
                const float4* row = (const float4*)(g_xT + (long)(yi * 64 + xi) * CC);
                float4 v = row[tid];
                acc.x += w * v.x; acc.y += w * v.y; acc.z += w * v.z; acc.w += w * v.w;
            }
        }
        ((float4*)(xr + ((long)j * NSLOT + s) * CC))[tid] = acc;
        if ((s / KK) == myg)
            *(float4*)&xs_s[s * CGC + 4 * tid - myg * CGC] = acc;
    }
    __syncthreads();

    if (tid < 72) {
        int h = tid / KK, k = tid % KK;
        float s = 0.f;
        #pragma unroll
        for (int g = 0; g < GG; g++) {
            const float* a = &qk_s[h * CC + g * CGC];
            const float* b = &xs_s[(g * KK + k) * CGC];
            #pragma unroll 8
            for (int c = 0; c < CGC; c++) s += a[c] * b[c];
        }
        lg[tid] = (s + qbk_s[h]) * 0.125f;
    }
    __syncthreads();

    if (tid < NH) {
        int h = tid;
        float mx = -1e30f;
        #pragma unroll
        for (int k = 0; k < KK; k++) mx = fmaxf(mx, lg[h * KK + k]);
        float e[KK], sm = 0.f;
        #pragma unroll
        for (int k = 0; k < KK; k++) { e[k] = expf(lg[h * KK + k] - mx); sm += e[k]; }
        float inv = 1.f / sm;
        #pragma unroll
        for (int k = 0; k < KK; k++) {
            float a = e[k] * inv;
            at[h * KK + k] = a;
            out[ATT_OFF + (long)h * NPT * KK + (long)j * KK + k] = a;
        }
    }
    __syncthreads();

    #pragma unroll
    for (int i = 0; i < 32; i++) {
        int o = i * 128 + tid;
        int h = o >> 9, c = o & 511, g = c >> 7, cc = c & 127;
        float s = 0.f;
        #pragma unroll
        for (int k = 0; k < KK; k++)
            s += at[h * KK + k] * xs_s[(g * KK + k) * CGC + cc];
        g_xsagg[(long)j * 4096 + o] = s;
    }
}

// ---------------- sigmoid of selected logit ----------------
__global__ void sig_kernel(const int* __restrict__ labels, float* __restrict__ out)
{
    int j = blockIdx.x * blockDim.x + threadIdx.x;
    if (j < NPT) {
        float v = out[(long)j * CC + labels[j]];
        out[SIG_OFF + j] = 1.f / (1.f + expf(-v));
    }
}

// ---------------- host ----------------
extern "C" void kernel_launch(void* const* d_in, const int* in_sizes, int n_in,
                              void* d_out, int out_size)
{
    const float* x   = (const float*)d_in[0];
    const int*   idx = (const int*)  d_in[1];
    const int*   lab = (const int*)  d_in[2];
    const float* wq  = (const float*)d_in[3];
    const float* bq  = (const float*)d_in[4];
    const float* wk  = (const float*)d_in[5];
    const float* bk  = (const float*)d_in[6];
    const float* wv  = (const float*)d_in[7];
    const float* bv  = (const float*)d_in[8];
    const float* wo  = (const float*)d_in[9];
    const float* bo  = (const float*)d_in[10];
    const float* ow1 = (const float*)d_in[11];
    const float* ob1 = (const float*)d_in[12];
    const float* g1  = (const float*)d_in[13];
    const float* b1  = (const float*)d_in[14];
    const float* ow2 = (const float*)d_in[15];
    const float* ob2 = (const float*)d_in[16];
    const float* g2  = (const float*)d_in[17];
    const float* b2  = (const float*)d_in[18];
    const float* ow3 = (const float*)d_in[19];
    float* out = (float*)d_out;

    float *xT, *qT, *t1, *t2, *qsel, *qk, *xsagg, *outT;
    cudaGetSymbolAddress((void**)&xT,    g_xT);
    cudaGetSymbolAddress((void**)&qT,    g_qT);
    cudaGetSymbolAddress((void**)&t1,    g_t1);
    cudaGetSymbolAddress((void**)&t2,    g_t2);
    cudaGetSymbolAddress((void**)&qsel,  g_qsel);
    cudaGetSymbolAddress((void**)&qk,    g_qk);
    cudaGetSymbolAddress((void**)&xsagg, g_xsagg);
    cudaGetSymbolAddress((void**)&outT,  g_outT);

    // 1) x -> xT (pixel-major)
    transpose_kernel<<<dim3(128, 16), dim3(32, 8)>>>(x);

    // 2) qT(P,C) = xT @ wq^T + bq
    gemm_mma_kernel<1><<<dim3(8, 32, 1), 128>>>(xT, wq, qT, bq,
        PP, CC, CC, CC, CC, CC, 0, 0, 0, 0);

    // 3) two depthwise+LN+GELU stages
    dw_ln_gelu_kernel<<<dim3(PP, GG), 128>>>(qT, t1, ow1, ob1, g1, b1,
        (long)CGC, CC);
    dw_ln_gelu_kernel<<<dim3(PP, GG), 128>>>(t1, t2, ow2, ob2, g2, b2,
        (long)PP * CGC, CGC);

    // 4) offsets -> sample coords; gather q_sel
    offset_kernel<<<NPT, 128>>>(idx, ow3);

    // 5) qk(j, h*512+c) = q_sel_h @ Wk_h   (8 batched, K=64, B is [K,N] layout)
    gemm_mma_kernel<0><<<dim3(8, 16, 8), 128>>>(qsel, wk, qk, nullptr,
        NPT, CC, DH, CC, CC, 4096, 64, (long)64 * 512, 512, 0);

    // 6) fused bilinear sampling (-> xr_sel) + logits + softmax + aggregation
    sample_attn_kernel<<<NPT, 128>>>(bk, out);

    // 7) outT(j, h*64+d) = xs_agg_h @ Wv_h^T + bv   (8 batched, N=64)
    gemm_mma_kernel<1><<<dim3(1, 16, 8), 128>>>(xsagg, wv, outT, bv,
        NPT, DH, CC, 4096, CC, CC, 512, (long)64 * 512, 64, 64);

    // 8) y(j, c) = outT @ wo^T + bo  -> directly into d_out
    gemm_mma_kernel<1><<<dim3(8, 16, 1), 128>>>(outT, wo, out, bo,
        NPT, CC, CC, CC, CC, CC, 0, 0, 0, 0);

    // 9) sig = sigmoid(y[j, labels[j]])
    sig_kernel<<<8, 256>>>(lab, out);
}

// round 5
// speedup vs baseline: 1.6153x; 1.2652x over previous
#include <cuda_runtime.h>
#include <cuda_bf16.h>
#include <math.h>
#include <stdint.h>

// ---------------- problem constants ----------------
#define HH 64
#define WW 64
#define PP 4096          // H*W
#define CC 512
#define CGC 128
#define GG 4
#define KK 9
#define NH 8
#define DH 64
#define NPT 2048         // n selected points
#define NSLOT 36         // G*K

// d_out layout: y (2048*512) | attn (8*2048*9) | xr_sel (2048*36*512) | sig (2048)
#define Y_OFF   0L
#define ATT_OFF 1048576L
#define XR_OFF  1196032L
#define SIG_OFF 38944768L

// ---------------- scratch (device globals; no runtime alloc) ----------------
__device__ float  g_xT  [(long)PP * CC];       // x transposed: (pixel, channel)
__device__ float  g_qT  [(long)PP * CC];       // q: (pixel, channel)
__device__ float  g_t1  [(long)GG * PP * CGC]; // (g, pixel, cc)
__device__ float  g_t2  [(long)GG * PP * CGC];
__device__ float2 g_meta[(long)NPT * NSLOT];   // (gy, gx) per (j, g*9+k)
__device__ float  g_qsel[(long)NPT * CC];      // q at selected points (j, c)
__device__ float  g_qk  [(long)NPT * 4096];    // (j, h*512+c)
__device__ float  g_xsagg[(long)NPT * 4096];   // (j, h*512+c)
__device__ float  g_outT[(long)NPT * CC];      // (j, h*64+d)

// ---------------- bf16 split helpers ----------------
__device__ __forceinline__ void split2(float v0, float v1, uint32_t& h, uint32_t& l) {
    uint32_t hw;
    asm("cvt.rn.bf16x2.f32 %0, %1, %2;" : "=r"(hw) : "f"(v1), "f"(v0));
    float f0 = __uint_as_float(hw << 16);
    float f1 = __uint_as_float(hw & 0xffff0000u);
    uint32_t lw;
    asm("cvt.rn.bf16x2.f32 %0, %1, %2;" : "=r"(lw) : "f"(v1 - f1), "f"(v0 - f0));
    h = hw; l = lw;
}
__device__ __forceinline__ void split1(float v, uint16_t& h, uint16_t& l) {
    __nv_bfloat16 hb = __float2bfloat16_rn(v);
    float hf = __bfloat162float(hb);
    __nv_bfloat16 lb = __float2bfloat16_rn(v - hf);
    h = __bfloat16_as_ushort(hb);
    l = __bfloat16_as_ushort(lb);
}
__device__ __forceinline__ void mma16(float* c, const uint32_t* a, const uint32_t* b) {
    asm volatile("mma.sync.aligned.m16n8k16.row.col.f32.bf16.bf16.f32 "
        "{%0,%1,%2,%3}, {%4,%5,%6,%7}, {%8,%9}, {%0,%1,%2,%3};"
        : "+f"(c[0]), "+f"(c[1]), "+f"(c[2]), "+f"(c[3])
        : "r"(a[0]), "r"(a[1]), "r"(a[2]), "r"(a[3]), "r"(b[0]), "r"(b[1]));
}

// ================= 3-term split-bf16 mma.sync GEMM, reg-prefetch pipelined =================
// C(M,N) = A(M,K) * B + bias.  TB=1: B[n][k] = Bg[n*ldb+k].  TB=0: B[k][n] = Bg[k*ldb+n].
// BM=128, BN=64, BK=16. 128 threads = 4 warps (2m x 2n), warp tile 64x32.
template<int TB>
__global__ __launch_bounds__(128) void gemm_mma_kernel(
    const float* __restrict__ A, const float* __restrict__ B,
    float* __restrict__ C, const float* __restrict__ bias,
    int M, int N, int Kd, int lda, int ldb, int ldc,
    long aOff, long bOff, long cOff, long biasOff)
{
    const int BM = 128, BN = 64, BK = 16;
    __shared__ __align__(16) uint32_t Ah[BM * 12], Al[BM * 12];
    __shared__ __align__(16) uint32_t Bh[BN * 12], Bl[BN * 12];

    int z = blockIdx.z;
    A += (long)z * aOff; B += (long)z * bOff; C += (long)z * cOff;
    if (bias) bias += (long)z * biasOff;

    int m0 = blockIdx.y * BM, n0 = blockIdx.x * BN;
    int tid = threadIdx.x, wid = tid >> 5, lane = tid & 31;
    int wm = (wid >> 1) * 64, wn = (wid & 1) * 32;
    int g = lane >> 2, tig = lane & 3;

    float acc[4][4][4];
    #pragma unroll
    for (int mi = 0; mi < 4; mi++)
        #pragma unroll
        for (int ni = 0; ni < 4; ni++)
            #pragma unroll
            for (int c = 0; c < 4; c++) acc[mi][ni][c] = 0.f;

    float4 ra[4];          // raw A prefetch (row tid, 16 floats)
    float4 rb[2];          // raw B prefetch

    const float* apBase = A + (long)(m0 + tid) * lda;
    auto ldA = [&](int k0) {
        const float* ap = apBase + k0;
        ra[0] = *(const float4*)(ap);
        ra[1] = *(const float4*)(ap + 4);
        ra[2] = *(const float4*)(ap + 8);
        ra[3] = *(const float4*)(ap + 12);
    };
    auto ldB = [&](int k0) {
        if (TB) {
            const float* bp = B + (long)(n0 + (tid >> 1)) * ldb + k0 + (tid & 1) * 8;
            rb[0] = *(const float4*)(bp);
            rb[1] = *(const float4*)(bp + 4);
        } else {
            #pragma unroll
            for (int i = 0; i < 2; i++) {
                int e = tid + i * 128;
                int k = e >> 4, n4 = (e & 15) * 4;
                rb[i] = *(const float4*)(B + (long)(k0 + k) * ldb + n0 + n4);
            }
        }
    };

    ldA(0); ldB(0);
    int nCh = Kd >> 4;
    for (int ch = 0; ch < nCh; ch++) {
        // ---- cvt + store current chunk to smem ----
        {
            uint4 h0, h1, l0, l1;
            split2(ra[0].x, ra[0].y, h0.x, l0.x); split2(ra[0].z, ra[0].w, h0.y, l0.y);
            split2(ra[1].x, ra[1].y, h0.z, l0.z); split2(ra[1].z, ra[1].w, h0.w, l0.w);
            split2(ra[2].x, ra[2].y, h1.x, l1.x); split2(ra[2].z, ra[2].w, h1.y, l1.y);
            split2(ra[3].x, ra[3].y, h1.z, l1.z); split2(ra[3].z, ra[3].w, h1.w, l1.w);
            *(uint4*)&Ah[tid * 12]     = h0;
            *(uint4*)&Ah[tid * 12 + 4] = h1;
            *(uint4*)&Al[tid * 12]     = l0;
            *(uint4*)&Al[tid * 12 + 4] = l1;
        }
        if (TB) {
            int n  = tid >> 1;
            int hf = (tid & 1) * 8;
            uint4 h, l;
            split2(rb[0].x, rb[0].y, h.x, l.x); split2(rb[0].z, rb[0].w, h.y, l.y);
            split2(rb[1].x, rb[1].y, h.z, l.z); split2(rb[1].z, rb[1].w, h.w, l.w);
            *(uint4*)&Bh[n * 12 + hf / 2] = h;
            *(uint4*)&Bl[n * 12 + hf / 2] = l;
        } else {
            uint16_t* bh16 = (uint16_t*)Bh;
            uint16_t* bl16 = (uint16_t*)Bl;
            #pragma unroll
            for (int i = 0; i < 2; i++) {
                int e = tid + i * 128;
                int k = e >> 4, n4 = (e & 15) * 4;
                float4 v = rb[i];
                uint16_t h, l;
                split1(v.x, h, l); bh16[(n4 + 0) * 24 + k] = h; bl16[(n4 + 0) * 24 + k] = l;
                split1(v.y, h, l); bh16[(n4 + 1) * 24 + k] = h; bl16[(n4 + 1) * 24 + k] = l;
                split1(v.z, h, l); bh16[(n4 + 2) * 24 + k] = h; bl16[(n4 + 2) * 24 + k] = l;
                split1(v.w, h, l); bh16[(n4 + 3) * 24 + k] = h; bl16[(n4 + 3) * 24 + k] = l;
            }
        }
        __syncthreads();

        // ---- prefetch next chunk (overlaps with MMA below) ----
        if (ch + 1 < nCh) { ldA((ch + 1) << 4); ldB((ch + 1) << 4); }

        // ---- fragments + MMA ----
        uint32_t ahf[4][4], alf[4][4], bhf[4][2], blf[4][2];
        #pragma unroll
        for (int mi = 0; mi < 4; mi++) {
            int mr = wm + mi * 16 + g;
            ahf[mi][0] = Ah[mr * 12 + tig];
            ahf[mi][1] = Ah[(mr + 8) * 12 + tig];
            ahf[mi][2] = Ah[mr * 12 + tig + 4];
            ahf[mi][3] = Ah[(mr + 8) * 12 + tig + 4];
            alf[mi][0] = Al[mr * 12 + tig];
            alf[mi][1] = Al[(mr + 8) * 12 + tig];
            alf[mi][2] = Al[mr * 12 + tig + 4];
            alf[mi][3] = Al[(mr + 8) * 12 + tig + 4];
        }
        #pragma unroll
        for (int ni = 0; ni < 4; ni++) {
            int nr = wn + ni * 8 + g;
            bhf[ni][0] = Bh[nr * 12 + tig];
            bhf[ni][1] = Bh[nr * 12 + tig + 4];
            blf[ni][0] = Bl[nr * 12 + tig];
            blf[ni][1] = Bl[nr * 12 + tig + 4];
        }
        #pragma unroll
        for (int mi = 0; mi < 4; mi++)
            #pragma unroll
            for (int ni = 0; ni < 4; ni++) {
                mma16(acc[mi][ni], ahf[mi], bhf[ni]);
                mma16(acc[mi][ni], ahf[mi], blf[ni]);
                mma16(acc[mi][ni], alf[mi], bhf[ni]);
            }
        __syncthreads();
    }

    // ---- epilogue ----
    #pragma unroll
    for (int ni = 0; ni < 4; ni++) {
        int col = n0 + wn + ni * 8 + 2 * tig;
        float b0 = 0.f, b1 = 0.f;
        if (bias) { b0 = bias[col]; b1 = bias[col + 1]; }
        #pragma unroll
        for (int mi = 0; mi < 4; mi++) {
            int row = m0 + wm + mi * 16 + g;
            float2 v0 = make_float2(acc[mi][ni][0] + b0, acc[mi][ni][1] + b1);
            float2 v1 = make_float2(acc[mi][ni][2] + b0, acc[mi][ni][3] + b1);
            *(float2*)(C + (long)row * ldc + col) = v0;
            *(float2*)(C + (long)(row + 8) * ldc + col) = v1;
        }
    }
}

// ---------------- transpose x (C,P) -> xT (P,C) ----------------
__global__ void transpose_kernel(const float* __restrict__ x)
{
    __shared__ float tile[32][33];
    int pb = blockIdx.x * 32;
    int cb = blockIdx.y * 32;
    int tx = threadIdx.x, ty = threadIdx.y;
    #pragma unroll
    for (int i = 0; i < 32; i += 8)
        tile[ty + i][tx] = x[(long)(cb + ty + i) * PP + pb + tx];
    __syncthreads();
    #pragma unroll
    for (int i = 0; i < 32; i += 8)
        g_xT[(long)(pb + ty + i) * CC + cb + tx] = tile[tx][ty + i];
}

// ---------------- depthwise3x3 + LayerNorm(channels) + GELU ----------------
__global__ void dw_ln_gelu_kernel(const float* __restrict__ in, float* __restrict__ outp,
                                  const float* __restrict__ w, const float* __restrict__ cb,
                                  const float* __restrict__ gamma, const float* __restrict__ beta,
                                  long gStride, int pixStride)
{
    int p = blockIdx.x;
    int g = blockIdx.y;
    int cc = threadIdx.x;           // 128
    int h = p >> 6, wx = p & 63;
    const float* base = in + (long)g * gStride + cc;

    float acc = cb[cc];
    #pragma unroll
    for (int dy = 0; dy < 3; dy++) {
        int yy = h + dy - 1;
        if ((unsigned)yy < 64u) {
            #pragma unroll
            for (int dx = 0; dx < 3; dx++) {
                int xx = wx + dx - 1;
                if ((unsigned)xx < 64u)
                    acc += base[(long)(yy * 64 + xx) * pixStride] * w[cc * 9 + dy * 3 + dx];
            }
        }
    }
    float s1 = acc, s2 = acc * acc;
    #pragma unroll
    for (int o = 16; o > 0; o >>= 1) {
        s1 += __shfl_xor_sync(0xffffffffu, s1, o);
        s2 += __shfl_xor_sync(0xffffffffu, s2, o);
    }
    __shared__ float r1[4], r2[4];
    int warp = cc >> 5, lane = cc & 31;
    if (lane == 0) { r1[warp] = s1; r2[warp] = s2; }
    __syncthreads();
    float t1s = r1[0] + r1[1] + r1[2] + r1[3];
    float t2s = r2[0] + r2[1] + r2[2] + r2[3];
    float mean = t1s * (1.f / 128.f);
    float var  = fmaxf(t2s * (1.f / 128.f) - mean * mean, 0.f);
    float nv = (acc - mean) * rsqrtf(var + 1e-5f) * gamma[cc] + beta[cc];
    float ge = 0.5f * nv * (1.f + erff(nv * 0.70710678118654752f));
    outp[((long)g * PP + p) * CGC + cc] = ge;
}

// ---------------- offsets + sample coords at selected points; gather q_sel ----------------
__global__ void offset_kernel(const int* __restrict__ idx, const float* __restrict__ ow3)
{
    int j = blockIdx.x;
    int tid = threadIdx.x;          // 128
    int warp = tid >> 5, lane = tid & 31;
    __shared__ float tv[128];
    __shared__ float offv[18];
    int iy = idx[2 * j], ix = idx[2 * j + 1];
    int p = iy * 64 + ix;

    const float4* qrow = (const float4*)(g_qT + (long)p * CC);
    float4* qs = (float4*)(g_qsel + (long)j * CC);
    qs[tid] = qrow[tid];

    for (int g = 0; g < GG; g++) {
        tv[tid] = g_t2[((long)g * PP + p) * CGC + tid];
        __syncthreads();
        // 18 dot products of length 128, warp-parallel
        for (int o = warp; o < 18; o += 4) {
            float s = 0.f;
            #pragma unroll
            for (int c = lane; c < 128; c += 32)
                s += tv[c] * ow3[o * 128 + c];
            #pragma unroll
            for (int off = 16; off > 0; off >>= 1)
                s += __shfl_xor_sync(0xffffffffu, s, off);
            if (lane == 0) offv[o] = s;
        }
        __syncthreads();
        if (tid < KK) {
            int k = tid, dy = k / 3, dx = k % 3;
            float oy = tanhf(offv[2 * k])     * (1.f / 32.f);
            float ox = tanhf(offv[2 * k + 1]) * (1.f / 32.f);
            int iyc = min(max(iy + dy - 1, 0), 63);
            int ixc = min(max(ix + dx - 1, 0), 63);
            float ry = (iyc + 0.5f) * (1.f / 32.f) - 1.f;
            float rx = (ixc + 0.5f) * (1.f / 32.f) - 1.f;
            float gy = (oy + ry + 1.f) * 31.5f;
            float gx = (ox + rx + 1.f) * 31.5f;
            g_meta[(long)j * NSLOT + g * KK + k] = make_float2(gy, gx);
        }
        __syncthreads();
    }
}

// ---------------- fused bilinear sampler + attention (256 threads, 2 slots in flight) ----
__global__ __launch_bounds__(256) void sample_attn_kernel(
    const float* __restrict__ bk, float* __restrict__ out)
{
    __shared__ float xs_s[NSLOT * CGC];   // 18KB: diagonal slice
    __shared__ float qk_s[4096];          // 16KB
    __shared__ float qbk_s[NH];
    __shared__ float lg[72];
    __shared__ float at[72];
    int j = blockIdx.x, tid = threadIdx.x;  // 256
    int ct = tid & 127;                     // channel-thread (4 ch via float4)
    int half = tid >> 7;
    float* xr = out + XR_OFF;
    int myg = ct >> 5;                      // group owned by this thread's channels

    #pragma unroll
    for (int i = 0; i < 16; i++)
        qk_s[i * 256 + tid] = g_qk[(long)j * 4096 + i * 256 + tid];
    if (tid < NH) {
        float s = 0.f;
        for (int d = 0; d < DH; d++)
            s += g_qsel[(long)j * CC + tid * DH + d] * bk[tid * DH + d];
        qbk_s[tid] = s;
    }

    #pragma unroll 2
    for (int s2 = 0; s2 < 18; s2++) {
        int s = s2 * 2 + half;
        float2 m = g_meta[(long)j * NSLOT + s];
        float gy = m.x, gx = m.y;
        float y0 = floorf(gy), x0 = floorf(gx);
        float wy1 = gy - y0, wy0 = 1.f - wy1;
        float wx1 = gx - x0, wx0 = 1.f - wx1;
        float4 acc = make_float4(0.f, 0.f, 0.f, 0.f);
        #pragma unroll
        for (int t = 0; t < 4; t++) {
            float yy = y0 + (float)(t >> 1);
            float xx = x0 + (float)(t & 1);
            float w = ((t >> 1) ? wy1 : wy0) * ((t & 1) ? wx1 : wx0);
            bool ok = (yy >= 0.f) && (yy <= 63.f) && (xx >= 0.f) && (xx <= 63.f);
            if (ok && w != 0.f) {
                int yi = (int)yy, xi = (int)xx;
                const float4* row = (const float4*)(g_xT + (long)(yi * 64 + xi) * CC);
                float4 v = row[ct];
                acc.x += w * v.x; acc.y += w * v.y; acc.z += w * v.z; acc.w += w * v.w;
            }
        }
        ((float4*)(xr + ((long)j * NSLOT + s) * CC))[ct] = acc;
        if ((s / KK) == myg)
            *(float4*)&xs_s[s * CGC + 4 * ct - myg * CGC] = acc;
    }
    __syncthreads();

    if (tid < 72) {
        int h = tid / KK, k = tid % KK;
        float s = 0.f;
        #pragma unroll
        for (int g = 0; g < GG; g++) {
            const float* a = &qk_s[h * CC + g * CGC];
            const float* b = &xs_s[(g * KK + k) * CGC];
            #pragma unroll 8
            for (int c = 0; c < CGC; c++) s += a[c] * b[c];
        }
        lg[tid] = (s + qbk_s[h]) * 0.125f;
    }
    __syncthreads();

    if (tid < NH) {
        int h = tid;
        float mx = -1e30f;
        #pragma unroll
        for (int k = 0; k < KK; k++) mx = fmaxf(mx, lg[h * KK + k]);
        float e[KK], sm = 0.f;
        #pragma unroll
        for (int k = 0; k < KK; k++) { e[k] = expf(lg[h * KK + k] - mx); sm += e[k]; }
        float inv = 1.f / sm;
        #pragma unroll
        for (int k = 0; k < KK; k++) {
            float a = e[k] * inv;
            at[h * KK + k] = a;
            out[ATT_OFF + (long)h * NPT * KK + (long)j * KK + k] = a;
        }
    }
    __syncthreads();

    #pragma unroll
    for (int i = 0; i < 16; i++) {
        int o = i * 256 + tid;
        int h = o >> 9, c = o & 511, g = c >> 7, cc = c & 127;
        float s = 0.f;
        #pragma unroll
        for (int k = 0; k < KK; k++)
            s += at[h * KK + k] * xs_s[(g * KK + k) * CGC + cc];
        g_xsagg[(long)j * 4096 + o] = s;
    }
}

// ---------------- sigmoid of selected logit ----------------
__global__ void sig_kernel(const int* __restrict__ labels, float* __restrict__ out)
{
    int j = blockIdx.x * blockDim.x + threadIdx.x;
    if (j < NPT) {
        float v = out[(long)j * CC + labels[j]];
        out[SIG_OFF + j] = 1.f / (1.f + expf(-v));
    }
}

// ---------------- host ----------------
extern "C" void kernel_launch(void* const* d_in, const int* in_sizes, int n_in,
                              void* d_out, int out_size)
{
    const float* x   = (const float*)d_in[0];
    const int*   idx = (const int*)  d_in[1];
    const int*   lab = (const int*)  d_in[2];
    const float* wq  = (const float*)d_in[3];
    const float* bq  = (const float*)d_in[4];
    const float* wk  = (const float*)d_in[5];
    const float* bk  = (const float*)d_in[6];
    const float* wv  = (const float*)d_in[7];
    const float* bv  = (const float*)d_in[8];
    const float* wo  = (const float*)d_in[9];
    const float* bo  = (const float*)d_in[10];
    const float* ow1 = (const float*)d_in[11];
    const float* ob1 = (const float*)d_in[12];
    const float* g1  = (const float*)d_in[13];
    const float* b1  = (const float*)d_in[14];
    const float* ow2 = (const float*)d_in[15];
    const float* ob2 = (const float*)d_in[16];
    const float* g2  = (const float*)d_in[17];
    const float* b2  = (const float*)d_in[18];
    const float* ow3 = (const float*)d_in[19];
    float* out = (float*)d_out;

    float *xT, *qT, *t1, *t2, *qsel, *qk, *xsagg, *outT;
    cudaGetSymbolAddress((void**)&xT,    g_xT);
    cudaGetSymbolAddress((void**)&qT,    g_qT);
    cudaGetSymbolAddress((void**)&t1,    g_t1);
    cudaGetSymbolAddress((void**)&t2,    g_t2);
    cudaGetSymbolAddress((void**)&qsel,  g_qsel);
    cudaGetSymbolAddress((void**)&qk,    g_qk);
    cudaGetSymbolAddress((void**)&xsagg, g_xsagg);
    cudaGetSymbolAddress((void**)&outT,  g_outT);

    // 1) x -> xT (pixel-major)
    transpose_kernel<<<dim3(128, 16), dim3(32, 8)>>>(x);

    // 2) qT(P,C) = xT @ wq^T + bq
    gemm_mma_kernel<1><<<dim3(8, 32, 1), 128>>>(xT, wq, qT, bq,
        PP, CC, CC, CC, CC, CC, 0, 0, 0, 0);

    // 3) two depthwise+LN+GELU stages
    dw_ln_gelu_kernel<<<dim3(PP, GG), 128>>>(qT, t1, ow1, ob1, g1, b1,
        (long)CGC, CC);
    dw_ln_gelu_kernel<<<dim3(PP, GG), 128>>>(t1, t2, ow2, ob2, g2, b2,
        (long)PP * CGC, CGC);

    // 4) offsets -> sample coords; gather q_sel
    offset_kernel<<<NPT, 128>>>(idx, ow3);

    // 5) qk(j, h*512+c) = q_sel_h @ Wk_h   (8 batched, K=64, B is [K,N] layout)
    gemm_mma_kernel<0><<<dim3(8, 16, 8), 128>>>(qsel, wk, qk, nullptr,
        NPT, CC, DH, CC, CC, 4096, 64, (long)64 * 512, 512, 0);

    // 6) fused bilinear sampling (-> xr_sel) + logits + softmax + aggregation
    sample_attn_kernel<<<NPT, 256>>>(bk, out);

    // 7) outT(j, h*64+d) = xs_agg_h @ Wv_h^T + bv   (8 batched, N=64)
    gemm_mma_kernel<1><<<dim3(1, 16, 8), 128>>>(xsagg, wv, outT, bv,
        NPT, DH, CC, 4096, CC, CC, 512, (long)64 * 512, 64, 64);

    // 8) y(j, c) = outT @ wo^T + bo  -> directly into d_out
    gemm_mma_kernel<1><<<dim3(8, 16, 1), 128>>>(outT, wo, out, bo,
        NPT, CC, CC, CC, CC, CC, 0, 0, 0, 0);

    // 9) sig = sigmoid(y[j, labels[j]])
    sig_kernel<<<8, 256>>>(lab, out);
}

// round 6
// speedup vs baseline: 1.6476x; 1.0200x over previous
#include <cuda_runtime.h>
#include <cuda_bf16.h>
#include <math.h>
#include <stdint.h>

// ---------------- problem constants ----------------
#define HH 64
#define WW 64
#define PP 4096          // H*W
#define CC 512
#define CGC 128
#define GG 4
#define KK 9
#define NH 8
#define DH 64
#define NPT 2048         // n selected points
#define NSLOT 36         // G*K

// d_out layout: y (2048*512) | attn (8*2048*9) | xr_sel (2048*36*512) | sig (2048)
#define Y_OFF   0L
#define ATT_OFF 1048576L
#define XR_OFF  1196032L
#define SIG_OFF 38944768L

// ---------------- scratch (device globals; no runtime alloc) ----------------
__device__ float    g_xT  [(long)PP * CC];      // x transposed (pixel, channel) fp32
__device__ uint16_t g_xTh [(long)PP * CC];      // bf16 hi
__device__ uint16_t g_xTl [(long)PP * CC];      // bf16 lo
__device__ float    g_qT  [(long)PP * CC];
__device__ float    g_t1  [(long)GG * PP * CGC];
__device__ float    g_t2  [(long)GG * PP * CGC];
__device__ float2   g_meta[(long)NPT * NSLOT];
__device__ uint16_t g_qselh[(long)NPT * CC];
__device__ uint16_t g_qsell[(long)NPT * CC];
__device__ float    g_qbk [(long)NPT * NH];
__device__ float    g_qk  [(long)NPT * 4096];
__device__ uint16_t g_xsh [(long)NPT * 4096];   // xsagg split
__device__ uint16_t g_xsl [(long)NPT * 4096];
__device__ uint16_t g_outTh[(long)NPT * CC];
__device__ uint16_t g_outTl[(long)NPT * CC];
__device__ uint16_t g_wh  [4L * 262144];        // wq|wk|wv|wo hi
__device__ uint16_t g_wl  [4L * 262144];        // lo

// ---------------- bf16 split helpers ----------------
__device__ __forceinline__ void split2(float v0, float v1, uint32_t& h, uint32_t& l) {
    uint32_t hw;
    asm("cvt.rn.bf16x2.f32 %0, %1, %2;" : "=r"(hw) : "f"(v1), "f"(v0));
    float f0 = __uint_as_float(hw << 16);
    float f1 = __uint_as_float(hw & 0xffff0000u);
    uint32_t lw;
    asm("cvt.rn.bf16x2.f32 %0, %1, %2;" : "=r"(lw) : "f"(v1 - f1), "f"(v0 - f0));
    h = hw; l = lw;
}
__device__ __forceinline__ void split1(float v, uint16_t& h, uint16_t& l) {
    __nv_bfloat16 hb = __float2bfloat16_rn(v);
    float hf = __bfloat162float(hb);
    __nv_bfloat16 lb = __float2bfloat16_rn(v - hf);
    h = __bfloat16_as_ushort(hb);
    l = __bfloat16_as_ushort(lb);
}
__device__ __forceinline__ void mma16(float* c, const uint32_t* a, const uint32_t* b) {
    asm volatile("mma.sync.aligned.m16n8k16.row.col.f32.bf16.bf16.f32 "
        "{%0,%1,%2,%3}, {%4,%5,%6,%7}, {%8,%9}, {%0,%1,%2,%3};"
        : "+f"(c[0]), "+f"(c[1]), "+f"(c[2]), "+f"(c[3])
        : "r"(a[0]), "r"(a[1]), "r"(a[2]), "r"(a[3]), "r"(b[0]), "r"(b[1]));
}

// ---------------- weight pre-split ----------------
__global__ void split_w_kernel(const float* __restrict__ w0, const float* __restrict__ w1,
                               const float* __restrict__ w2, const float* __restrict__ w3)
{
    int t = blockIdx.x * blockDim.x + threadIdx.x;   // 524288 float2 items
    int m = t >> 17;
    int i = t & 131071;
    const float* src = (m == 0) ? w0 : (m == 1) ? w1 : (m == 2) ? w2 : w3;
    float2 v = ((const float2*)src)[i];
    uint32_t h, l;
    split2(v.x, v.y, h, l);
    ((uint32_t*)(g_wh + (long)m * 262144))[i] = h;
    ((uint32_t*)(g_wl + (long)m * 262144))[i] = l;
}

// ================= pre-split bf16 3-term GEMM, reg-prefetch pipelined =================
// C(M,N) = A(M,K) * B + bias on bf16 hi/lo operands (3 of 4 cross terms).
// TB=1: B[n][k] at Bg[n*ldb+k].  TB=0: B[k][n] at Bg[k*ldb+n].
// BN=64 fixed. BM in {64,128}. 128 threads = 4 warps (2m x 2n).
template<int BM, int TB, int SPLITOUT>
__global__ __launch_bounds__(128) void gemm2_kernel(
    const uint16_t* __restrict__ Ah_g, const uint16_t* __restrict__ Al_g,
    const uint16_t* __restrict__ Bh_g, const uint16_t* __restrict__ Bl_g,
    float* __restrict__ C, uint16_t* __restrict__ Ch, uint16_t* __restrict__ Cl,
    const float* __restrict__ bias,
    int Kd, int lda, int ldb, int ldc,
    long aOff, long bOff, long cOff, long biasOff)
{
    const int BN = 64, MI = BM / 32;
    __shared__ __align__(16) uint32_t Ah[BM * 12], Al[BM * 12];
    __shared__ __align__(16) uint32_t Bh[BN * 12], Bl[BN * 12];

    int z = blockIdx.z;
    Ah_g += (long)z * aOff; Al_g += (long)z * aOff;
    Bh_g += (long)z * bOff; Bl_g += (long)z * bOff;
    if (C)  C  += (long)z * cOff;
    if (Ch) { Ch += (long)z * cOff; Cl += (long)z * cOff; }
    if (bias) bias += (long)z * biasOff;

    int m0 = blockIdx.y * BM, n0 = blockIdx.x * BN;
    int tid = threadIdx.x, wid = tid >> 5, lane = tid & 31;
    int wm = (wid >> 1) * (MI * 16), wn = (wid & 1) * 32;
    int g = lane >> 2, tig = lane & 3;

    float acc[MI][4][4];
    #pragma unroll
    for (int mi = 0; mi < MI; mi++)
        #pragma unroll
        for (int ni = 0; ni < 4; ni++)
            #pragma unroll
            for (int c = 0; c < 4; c++) acc[mi][ni][c] = 0.f;

    const int NA = (BM == 128) ? 2 : 1;
    uint4 rah[NA], ral[NA], rbh, rbl;

    // A addressing
    int arow = (BM == 128) ? tid : (tid >> 1);
    int acol = (BM == 128) ? 0 : (tid & 1) * 8;
    const uint16_t* apH = Ah_g + (long)(m0 + arow) * lda + acol;
    const uint16_t* apL = Al_g + (long)(m0 + arow) * lda + acol;
    auto ldA = [&](int k0) {
        #pragma unroll
        for (int i = 0; i < NA; i++) {
            rah[i] = *(const uint4*)(apH + k0 + i * 8);
            ral[i] = *(const uint4*)(apL + k0 + i * 8);
        }
    };
    // B addressing
    int brow = TB ? (tid >> 1) : (tid >> 3);           // TB=1: n row; TB=0: k row
    int bcol = TB ? (tid & 1) * 8 : (tid & 7) * 8;
    const uint16_t* bpH = Bh_g + (long)(TB ? (n0 + brow) : brow) * ldb + (TB ? 0 : n0) + bcol;
    const uint16_t* bpL = Bl_g + (long)(TB ? (n0 + brow) : brow) * ldb + (TB ? 0 : n0) + bcol;
    auto ldB = [&](int k0) {
        if (TB) {
            rbh = *(const uint4*)(bpH + k0);
            rbl = *(const uint4*)(bpL + k0);
        } else {
            rbh = *(const uint4*)(bpH + (long)k0 * ldb);
            rbl = *(const uint4*)(bpL + (long)k0 * ldb);
        }
    };

    ldA(0); ldB(0);
    int nCh = Kd >> 4;
    for (int ch = 0; ch < nCh; ch++) {
        // ---- store current chunk to smem ----
        if (BM == 128) {
            *(uint4*)&Ah[tid * 12]     = rah[0];
            *(uint4*)&Ah[tid * 12 + 4] = rah[1];
            *(uint4*)&Al[tid * 12]     = ral[0];
            *(uint4*)&Al[tid * 12 + 4] = ral[1];
        } else {
            *(uint4*)&Ah[arow * 12 + (acol >> 1)] = rah[0];
            *(uint4*)&Al[arow * 12 + (acol >> 1)] = ral[0];
        }
        if (TB) {
            *(uint4*)&Bh[brow * 12 + (bcol >> 1)] = rbh;
            *(uint4*)&Bl[brow * 12 + (bcol >> 1)] = rbl;
        } else {
            uint16_t* bh16 = (uint16_t*)Bh;
            uint16_t* bl16 = (uint16_t*)Bl;
            const uint16_t* sh = (const uint16_t*)&rbh;
            const uint16_t* sl = (const uint16_t*)&rbl;
            #pragma unroll
            for (int i = 0; i < 8; i++) {
                bh16[(bcol + i) * 24 + brow] = sh[i];
                bl16[(bcol + i) * 24 + brow] = sl[i];
            }
        }
        __syncthreads();

        // ---- prefetch next chunk (overlaps MMA) ----
        if (ch + 1 < nCh) { ldA((ch + 1) << 4); ldB((ch + 1) << 4); }

        // ---- fragments + MMA ----
        uint32_t ahf[MI][4], alf[MI][4], bhf[4][2], blf[4][2];
        #pragma unroll
        for (int mi = 0; mi < MI; mi++) {
            int mr = wm + mi * 16 + g;
            ahf[mi][0] = Ah[mr * 12 + tig];
            ahf[mi][1] = Ah[(mr + 8) * 12 + tig];
            ahf[mi][2] = Ah[mr * 12 + tig + 4];
            ahf[mi][3] = Ah[(mr + 8) * 12 + tig + 4];
            alf[mi][0] = Al[mr * 12 + tig];
            alf[mi][1] = Al[(mr + 8) * 12 + tig];
            alf[mi][2] = Al[mr * 12 + tig + 4];
            alf[mi][3] = Al[(mr + 8) * 12 + tig + 4];
        }
        #pragma unroll
        for (int ni = 0; ni < 4; ni++) {
            int nr = wn + ni * 8 + g;
            bhf[ni][0] = Bh[nr * 12 + tig];
            bhf[ni][1] = Bh[nr * 12 + tig + 4];
            blf[ni][0] = Bl[nr * 12 + tig];
            blf[ni][1] = Bl[nr * 12 + tig + 4];
        }
        #pragma unroll
        for (int mi = 0; mi < MI; mi++)
            #pragma unroll
            for (int ni = 0; ni < 4; ni++) {
                mma16(acc[mi][ni], ahf[mi], bhf[ni]);
                mma16(acc[mi][ni], ahf[mi], blf[ni]);
                mma16(acc[mi][ni], alf[mi], bhf[ni]);
            }
        __syncthreads();
    }

    // ---- epilogue ----
    #pragma unroll
    for (int ni = 0; ni < 4; ni++) {
        int col = n0 + wn + ni * 8 + 2 * tig;
        float b0 = 0.f, b1 = 0.f;
        if (bias) { b0 = bias[col]; b1 = bias[col + 1]; }
        #pragma unroll
        for (int mi = 0; mi < MI; mi++) {
            int row = m0 + wm + mi * 16 + g;
            float v00 = acc[mi][ni][0] + b0, v01 = acc[mi][ni][1] + b1;
            float v10 = acc[mi][ni][2] + b0, v11 = acc[mi][ni][3] + b1;
            if (SPLITOUT) {
                uint16_t h, l;
                split1(v00, h, l); Ch[(long)row * ldc + col] = h;     Cl[(long)row * ldc + col] = l;
                split1(v01, h, l); Ch[(long)row * ldc + col + 1] = h; Cl[(long)row * ldc + col + 1] = l;
                split1(v10, h, l); Ch[(long)(row + 8) * ldc + col] = h;     Cl[(long)(row + 8) * ldc + col] = l;
                split1(v11, h, l); Ch[(long)(row + 8) * ldc + col + 1] = h; Cl[(long)(row + 8) * ldc + col + 1] = l;
            } else {
                *(float2*)(C + (long)row * ldc + col) = make_float2(v00, v01);
                *(float2*)(C + (long)(row + 8) * ldc + col) = make_float2(v10, v11);
            }
        }
    }
}

// ---------------- transpose x (C,P) -> xT (P,C) fp32 + split bf16 ----------------
__global__ void transpose_kernel(const float* __restrict__ x)
{
    __shared__ float tile[32][33];
    int pb = blockIdx.x * 32;
    int cb = blockIdx.y * 32;
    int tx = threadIdx.x, ty = threadIdx.y;
    #pragma unroll
    for (int i = 0; i < 32; i += 8)
        tile[ty + i][tx] = x[(long)(cb + ty + i) * PP + pb + tx];
    __syncthreads();
    #pragma unroll
    for (int i = 0; i < 32; i += 8) {
        float v = tile[tx][ty + i];
        long o = (long)(pb + ty + i) * CC + cb + tx;
        g_xT[o] = v;
        uint16_t h, l;
        split1(v, h, l);
        g_xTh[o] = h;
        g_xTl[o] = l;
    }
}

// ---------------- depthwise3x3 + LayerNorm(channels) + GELU ----------------
__global__ void dw_ln_gelu_kernel(const float* __restrict__ in, float* __restrict__ outp,
                                  const float* __restrict__ w, const float* __restrict__ cb,
                                  const float* __restrict__ gamma, const float* __restrict__ beta,
                                  long gStride, int pixStride)
{
    int p = blockIdx.x;
    int g = blockIdx.y;
    int cc = threadIdx.x;           // 128
    int h = p >> 6, wx = p & 63;
    const float* base = in + (long)g * gStride + cc;

    float acc = cb[cc];
    #pragma unroll
    for (int dy = 0; dy < 3; dy++) {
        int yy = h + dy - 1;
        if ((unsigned)yy < 64u) {
            #pragma unroll
            for (int dx = 0; dx < 3; dx++) {
                int xx = wx + dx - 1;
                if ((unsigned)xx < 64u)
                    acc += base[(long)(yy * 64 + xx) * pixStride] * w[cc * 9 + dy * 3 + dx];
            }
        }
    }
    float s1 = acc, s2 = acc * acc;
    #pragma unroll
    for (int o = 16; o > 0; o >>= 1) {
        s1 += __shfl_xor_sync(0xffffffffu, s1, o);
        s2 += __shfl_xor_sync(0xffffffffu, s2, o);
    }
    __shared__ float r1[4], r2[4];
    int warp = cc >> 5, lane = cc & 31;
    if (lane == 0) { r1[warp] = s1; r2[warp] = s2; }
    __syncthreads();
    float t1s = r1[0] + r1[1] + r1[2] + r1[3];
    float t2s = r2[0] + r2[1] + r2[2] + r2[3];
    float mean = t1s * (1.f / 128.f);
    float var  = fmaxf(t2s * (1.f / 128.f) - mean * mean, 0.f);
    float nv = (acc - mean) * rsqrtf(var + 1e-5f) * gamma[cc] + beta[cc];
    float ge = 0.5f * nv * (1.f + erff(nv * 0.70710678118654752f));
    outp[((long)g * PP + p) * CGC + cc] = ge;
}

// ---------------- offsets + coords; qsel split; qbk dot ----------------
__global__ void offset_kernel(const int* __restrict__ idx, const float* __restrict__ ow3,
                              const float* __restrict__ bk)
{
    int j = blockIdx.x;
    int tid = threadIdx.x;          // 128
    int warp = tid >> 5, lane = tid & 31;
    __shared__ float tv[128];
    __shared__ float offv[18];
    int iy = idx[2 * j], ix = idx[2 * j + 1];
    int p = iy * 64 + ix;

    // gather q at this point; write split + qbk dot
    {
        float4 v = ((const float4*)(g_qT + (long)p * CC))[tid];
        uint32_t h01, l01, h23, l23;
        split2(v.x, v.y, h01, l01);
        split2(v.z, v.w, h23, l23);
        ((uint2*)(g_qselh + (long)j * CC))[tid] = make_uint2(h01, h23);
        ((uint2*)(g_qsell + (long)j * CC))[tid] = make_uint2(l01, l23);
        float4 b = ((const float4*)bk)[tid];
        float s = v.x * b.x + v.y * b.y + v.z * b.z + v.w * b.w;
        #pragma unroll
        for (int o = 8; o > 0; o >>= 1)
            s += __shfl_xor_sync(0xffffffffu, s, o);
        if ((tid & 15) == 0) g_qbk[(long)j * NH + (tid >> 4)] = s;
    }

    for (int g = 0; g < GG; g++) {
        tv[tid] = g_t2[((long)g * PP + p) * CGC + tid];
        __syncthreads();
        for (int o = warp; o < 18; o += 4) {
            float s = 0.f;
            #pragma unroll
            for (int c = lane; c < 128; c += 32)
                s += tv[c] * ow3[o * 128 + c];
            #pragma unroll
            for (int off = 16; off > 0; off >>= 1)
                s += __shfl_xor_sync(0xffffffffu, s, off);
            if (lane == 0) offv[o] = s;
        }
        __syncthreads();
        if (tid < KK) {
            int k = tid, dy = k / 3, dx = k % 3;
            float oy = tanhf(offv[2 * k])     * (1.f / 32.f);
            float ox = tanhf(offv[2 * k + 1]) * (1.f / 32.f);
            int iyc = min(max(iy + dy - 1, 0), 63);
            int ixc = min(max(ix + dx - 1, 0), 63);
            float ry = (iyc + 0.5f) * (1.f / 32.f) - 1.f;
            float rx = (ixc + 0.5f) * (1.f / 32.f) - 1.f;
            float gy = (oy + ry + 1.f) * 31.5f;
            float gx = (ox + rx + 1.f) * 31.5f;
            g_meta[(long)j * NSLOT + g * KK + k] = make_float2(gy, gx);
        }
        __syncthreads();
    }
}

// ---------------- fused bilinear sampler + attention (256 threads) ----------------
__global__ __launch_bounds__(256) void sample_attn_kernel(float* __restrict__ out)
{
    __shared__ float xs_s[NSLOT * CGC];   // 18KB diagonal slice
    __shared__ float qk_s[4096];          // 16KB
    __shared__ float lg[72];
    __shared__ float at[72];
    int j = blockIdx.x, tid = threadIdx.x;  // 256
    int ct = tid & 127;
    int half = tid >> 7;
    float* xr = out + XR_OFF;
    int myg = ct >> 5;

    #pragma unroll
    for (int i = 0; i < 16; i++)
        qk_s[i * 256 + tid] = g_qk[(long)j * 4096 + i * 256 + tid];

    #pragma unroll 2
    for (int s2 = 0; s2 < 18; s2++) {
        int s = s2 * 2 + half;
        float2 m = g_meta[(long)j * NSLOT + s];
        float gy = m.x, gx = m.y;
        float y0 = floorf(gy), x0 = floorf(gx);
        float wy1 = gy - y0, wy0 = 1.f - wy1;
        float wx1 = gx - x0, wx0 = 1.f - wx1;
        float4 acc = make_float4(0.f, 0.f, 0.f, 0.f);
        #pragma unroll
        for (int t = 0; t < 4; t++) {
            float yy = y0 + (float)(t >> 1);
            float xx = x0 + (float)(t & 1);
            float w = ((t >> 1) ? wy1 : wy0) * ((t & 1) ? wx1 : wx0);
            bool ok = (yy >= 0.f) && (yy <= 63.f) && (xx >= 0.f) && (xx <= 63.f);
            if (ok && w != 0.f) {
                int yi = (int)yy, xi = (int)xx;
                const float4* row = (const float4*)(g_xT + (long)(yi * 64 + xi) * CC);
                float4 v = row[ct];
                acc.x += w * v.x; acc.y += w * v.y; acc.z += w * v.z; acc.w += w * v.w;
            }
        }
        ((float4*)(xr + ((long)j * NSLOT + s) * CC))[ct] = acc;
        if ((s / KK) == myg)
            *(float4*)&xs_s[s * CGC + 4 * ct - myg * CGC] = acc;
    }
    __syncthreads();

    if (tid < 72) {
        int h = tid / KK, k = tid % KK;
        float s = 0.f;
        #pragma unroll
        for (int g = 0; g < GG; g++) {
            const float* a = &qk_s[h * CC + g * CGC];
            const float* b = &xs_s[(g * KK + k) * CGC];
            #pragma unroll 8
            for (int c = 0; c < CGC; c++) s += a[c] * b[c];
        }
        lg[tid] = (s + g_qbk[(long)j * NH + h]) * 0.125f;
    }
    __syncthreads();

    if (tid < NH) {
        int h = tid;
        float mx = -1e30f;
        #pragma unroll
        for (int k = 0; k < KK; k++) mx = fmaxf(mx, lg[h * KK + k]);
        float e[KK], sm = 0.f;
        #pragma unroll
        for (int k = 0; k < KK; k++) { e[k] = expf(lg[h * KK + k] - mx); sm += e[k]; }
        float inv = 1.f / sm;
        #pragma unroll
        for (int k = 0; k < KK; k++) {
            float a = e[k] * inv;
            at[h * KK + k] = a;
            out[ATT_OFF + (long)h * NPT * KK + (long)j * KK + k] = a;
        }
    }
    __syncthreads();

    #pragma unroll
    for (int i = 0; i < 16; i++) {
        int o = i * 256 + tid;
        int h = o >> 9, c = o & 511, g = c >> 7, cc = c & 127;
        float s = 0.f;
        #pragma unroll
        for (int k = 0; k < KK; k++)
            s += at[h * KK + k] * xs_s[(g * KK + k) * CGC + cc];
        uint16_t hh, ll;
        split1(s, hh, ll);
        g_xsh[(long)j * 4096 + o] = hh;
        g_xsl[(long)j * 4096 + o] = ll;
    }
}

// ---------------- sigmoid of selected logit ----------------
__global__ void sig_kernel(const int* __restrict__ labels, float* __restrict__ out)
{
    int j = blockIdx.x * blockDim.x + threadIdx.x;
    if (j < NPT) {
        float v = out[(long)j * CC + labels[j]];
        out[SIG_OFF + j] = 1.f / (1.f + expf(-v));
    }
}

// ---------------- host ----------------
extern "C" void kernel_launch(void* const* d_in, const int* in_sizes, int n_in,
                              void* d_out, int out_size)
{
    const float* x   = (const float*)d_in[0];
    const int*   idx = (const int*)  d_in[1];
    const int*   lab = (const int*)  d_in[2];
    const float* wq  = (const float*)d_in[3];
    const float* bq  = (const float*)d_in[4];
    const float* wk  = (const float*)d_in[5];
    const float* bk  = (const float*)d_in[6];
    const float* wv  = (const float*)d_in[7];
    const float* bv  = (const float*)d_in[8];
    const float* wo  = (const float*)d_in[9];
    const float* bo  = (const float*)d_in[10];
    const float* ow1 = (const float*)d_in[11];
    const float* ob1 = (const float*)d_in[12];
    const float* g1  = (const float*)d_in[13];
    const float* b1  = (const float*)d_in[14];
    const float* ow2 = (const float*)d_in[15];
    const float* ob2 = (const float*)d_in[16];
    const float* g2  = (const float*)d_in[17];
    const float* b2  = (const float*)d_in[18];
    const float* ow3 = (const float*)d_in[19];
    float* out = (float*)d_out;

    float *qT, *t1, *t2, *qk;
    uint16_t *xTh, *xTl, *qsh, *qsl, *xsh, *xsl, *oth, *otl, *wh, *wl;
    cudaGetSymbolAddress((void**)&qT,  g_qT);
    cudaGetSymbolAddress((void**)&t1,  g_t1);
    cudaGetSymbolAddress((void**)&t2,  g_t2);
    cudaGetSymbolAddress((void**)&qk,  g_qk);
    cudaGetSymbolAddress((void**)&xTh, g_xTh);
    cudaGetSymbolAddress((void**)&xTl, g_xTl);
    cudaGetSymbolAddress((void**)&qsh, g_qselh);
    cudaGetSymbolAddress((void**)&qsl, g_qsell);
    cudaGetSymbolAddress((void**)&xsh, g_xsh);
    cudaGetSymbolAddress((void**)&xsl, g_xsl);
    cudaGetSymbolAddress((void**)&oth, g_outTh);
    cudaGetSymbolAddress((void**)&otl, g_outTl);
    cudaGetSymbolAddress((void**)&wh,  g_wh);
    cudaGetSymbolAddress((void**)&wl,  g_wl);
    uint16_t *wqh = wh,            *wql = wl;
    uint16_t *wkh = wh + 262144,   *wkl = wl + 262144;
    uint16_t *wvh = wh + 524288,   *wvl = wl + 524288;
    uint16_t *woh = wh + 786432,   *wol = wl + 786432;

    // 0) split weights to bf16 hi/lo
    split_w_kernel<<<2048, 256>>>(wq, wk, wv, wo);

    // 1) x -> xT fp32 + split
    transpose_kernel<<<dim3(128, 16), dim3(32, 8)>>>(x);

    // 2) qT(P,C) = xT @ wq^T + bq
    gemm2_kernel<128, 1, 0><<<dim3(8, 32, 1), 128>>>(xTh, xTl, wqh, wql,
        qT, nullptr, nullptr, bq, CC, CC, CC, CC, 0, 0, 0, 0);

    // 3) two depthwise+LN+GELU stages
    dw_ln_gelu_kernel<<<dim3(PP, GG), 128>>>(qT, t1, ow1, ob1, g1, b1,
        (long)CGC, CC);
    dw_ln_gelu_kernel<<<dim3(PP, GG), 128>>>(t1, t2, ow2, ob2, g2, b2,
        (long)PP * CGC, CGC);

    // 4) offsets -> coords; qsel split; qbk
    offset_kernel<<<NPT, 128>>>(idx, ow3, bk);

    // 5) qk = q_sel_h @ Wk_h (8 batched, TB=0)
    gemm2_kernel<128, 0, 0><<<dim3(8, 16, 8), 128>>>(qsh, qsl, wkh, wkl,
        qk, nullptr, nullptr, nullptr, DH, CC, CC, 4096, 64, (long)64 * 512, 512, 0);

    // 6) fused sampling + attention -> xr_sel, attn, xsagg split
    sample_attn_kernel<<<NPT, 256>>>(out);

    // 7) outT = xsagg_h @ Wv_h^T + bv (8 batched, split output)
    gemm2_kernel<64, 1, 1><<<dim3(1, 32, 8), 128>>>(xsh, xsl, wvh, wvl,
        nullptr, oth, otl, bv, CC, 4096, CC, CC, 512, (long)64 * 512, 64, 64);

    // 8) y = outT @ wo^T + bo
    gemm2_kernel<64, 1, 0><<<dim3(8, 32, 1), 128>>>(oth, otl, woh, wol,
        out, nullptr, nullptr, bo, CC, CC, CC, CC, 0, 0, 0, 0);

    // 9) sig
    sig_kernel<<<8, 256>>>(lab, out);
}

// round 7
// speedup vs baseline: 2.1659x; 1.3146x over previous
#include <cuda_runtime.h>
#include <cuda_bf16.h>
#include <math.h>
#include <stdint.h>

// ---------------- problem constants ----------------
#define HH 64
#define WW 64
#define PP 4096
#define CC 512
#define CGC 128
#define GG 4
#define KK 9
#define NH 8
#define DH 64
#define NPT 2048
#define NSLOT 36

// d_out layout: y | attn | xr_sel | sig
#define Y_OFF   0L
#define ATT_OFF 1048576L
#define XR_OFF  1196032L
#define SIG_OFF 38944768L

// ---------------- scratch ----------------
__device__ float    g_xT  [(long)PP * CC];
__device__ uint16_t g_xTh [(long)PP * CC];
__device__ uint16_t g_xTl [(long)PP * CC];
__device__ float    g_qT  [(long)PP * CC];
__device__ float    g_t1  [(long)GG * PP * CGC];
__device__ float    g_t2  [(long)GG * PP * CGC];
__device__ float2   g_meta[(long)NPT * NSLOT];
__device__ uint16_t g_qselh[(long)NPT * CC];
__device__ uint16_t g_qsell[(long)NPT * CC];
__device__ float    g_qbk [(long)NPT * NH];
__device__ float    g_qk  [(long)NPT * 4096];
__device__ uint16_t g_xsh [(long)NPT * 4096];
__device__ uint16_t g_xsl [(long)NPT * 4096];
__device__ uint16_t g_outTh[(long)NPT * CC];
__device__ uint16_t g_outTl[(long)NPT * CC];
__device__ uint16_t g_wh  [4L * 262144];   // wq | wv | wo | wkT
__device__ uint16_t g_wl  [4L * 262144];

// ---------------- helpers ----------------
__device__ __forceinline__ void split2(float v0, float v1, uint32_t& h, uint32_t& l) {
    uint32_t hw;
    asm("cvt.rn.bf16x2.f32 %0, %1, %2;" : "=r"(hw) : "f"(v1), "f"(v0));
    float f0 = __uint_as_float(hw << 16);
    float f1 = __uint_as_float(hw & 0xffff0000u);
    uint32_t lw;
    asm("cvt.rn.bf16x2.f32 %0, %1, %2;" : "=r"(lw) : "f"(v1 - f1), "f"(v0 - f0));
    h = hw; l = lw;
}
__device__ __forceinline__ void split1(float v, uint16_t& h, uint16_t& l) {
    __nv_bfloat16 hb = __float2bfloat16_rn(v);
    float hf = __bfloat162float(hb);
    __nv_bfloat16 lb = __float2bfloat16_rn(v - hf);
    h = __bfloat16_as_ushort(hb);
    l = __bfloat16_as_ushort(lb);
}
__device__ __forceinline__ void mma16(float* c, const uint32_t* a, const uint32_t* b) {
    asm volatile("mma.sync.aligned.m16n8k16.row.col.f32.bf16.bf16.f32 "
        "{%0,%1,%2,%3}, {%4,%5,%6,%7}, {%8,%9}, {%0,%1,%2,%3};"
        : "+f"(c[0]), "+f"(c[1]), "+f"(c[2]), "+f"(c[3])
        : "r"(a[0]), "r"(a[1]), "r"(a[2]), "r"(a[3]), "r"(b[0]), "r"(b[1]));
}
__device__ __forceinline__ void cpa16(void* smem, const void* gmem) {
    uint32_t s = (uint32_t)__cvta_generic_to_shared(smem);
    asm volatile("cp.async.ca.shared.global [%0], [%1], 16;" :: "r"(s), "l"(gmem));
}

// ---------------- weight pre-split (wq, wv, wo straight) ----------------
__global__ void split_w_kernel(const float* __restrict__ w0, const float* __restrict__ w1,
                               const float* __restrict__ w2)
{
    int t = blockIdx.x * blockDim.x + threadIdx.x;   // 3*131072 float2 items
    int m = t >> 17;
    int i = t & 131071;
    const float* src = (m == 0) ? w0 : (m == 1) ? w1 : w2;
    float2 v = ((const float2*)src)[i];
    uint32_t h, l;
    split2(v.x, v.y, h, l);
    ((uint32_t*)(g_wh + (long)m * 262144))[i] = h;
    ((uint32_t*)(g_wl + (long)m * 262144))[i] = l;
}

// ---------------- wk transpose + split: wkT[(o>>6)*32768 + c*64 + (o&63)] = wk[o*512+c] ----
__global__ void wkT_kernel(const float* __restrict__ wk)
{
    __shared__ float tile[32][33];
    int o0 = blockIdx.x * 32, c0 = blockIdx.y * 32;
    int tx = threadIdx.x, ty = threadIdx.y;
    #pragma unroll
    for (int i = 0; i < 32; i += 8)
        tile[ty + i][tx] = wk[(o0 + ty + i) * 512 + c0 + tx];
    __syncthreads();
    #pragma unroll
    for (int i = 0; i < 32; i += 8) {
        int o = o0 + tx, c = c0 + ty + i;
        float v = tile[tx][ty + i];
        uint16_t h, l;
        split1(v, h, l);
        long dst = 786432L + (long)(o >> 6) * 32768 + (long)c * 64 + (o & 63);
        g_wh[dst] = h;
        g_wl[dst] = l;
    }
}

// ================= cp.async double-buffered split-bf16 GEMM =================
// C(M,N) = A(M,K) * B^T + bias, all operands pre-split bf16 hi/lo (3 cross terms).
// B[n][k] at Bg[n*ldb + k]. BM=128, BN=64, BK=16, 256 threads = 8 warps (4m x 2n).
template<int SPLITOUT>
__global__ __launch_bounds__(256) void gemm2_kernel(
    const uint16_t* __restrict__ Ah_g, const uint16_t* __restrict__ Al_g,
    const uint16_t* __restrict__ Bh_g, const uint16_t* __restrict__ Bl_g,
    float* __restrict__ C, uint16_t* __restrict__ Ch, uint16_t* __restrict__ Cl,
    const float* __restrict__ bias,
    int Kd, int lda, int ldb, int ldc,
    long aOff, long bOff, long cOff, long biasOff)
{
    const int BM = 128, BN = 64;
    __shared__ __align__(16) uint32_t Ah[2][BM * 12], Al[2][BM * 12];
    __shared__ __align__(16) uint32_t Bh[2][BN * 12], Bl[2][BN * 12];

    int z = blockIdx.z;
    Ah_g += (long)z * aOff; Al_g += (long)z * aOff;
    Bh_g += (long)z * bOff; Bl_g += (long)z * bOff;
    if (SPLITOUT) { Ch += (long)z * cOff; Cl += (long)z * cOff; }
    else          { C  += (long)z * cOff; }
    if (bias) bias += (long)z * biasOff;

    int m0 = blockIdx.y * BM, n0 = blockIdx.x * BN;
    int tid = threadIdx.x, wid = tid >> 5, lane = tid & 31;
    int wm = (wid >> 1) * 32, wn = (wid & 1) * 32;
    int g = lane >> 2, tig = lane & 3;

    // load mapping: A hi/lo 1 task each (row, half); B 1 task (hi for tid<128, lo else)
    int ar = tid >> 1, ah2 = tid & 1;
    const uint16_t* apH = Ah_g + (long)(m0 + ar) * lda + ah2 * 8;
    const uint16_t* apL = Al_g + (long)(m0 + ar) * lda + ah2 * 8;
    int bt = tid & 127;
    int bn = bt >> 1, bh2 = bt & 1;
    bool bHi = tid < 128;
    const uint16_t* bp = (bHi ? Bh_g : Bl_g) + (long)(n0 + bn) * ldb + bh2 * 8;

    auto loadChunk = [&](int ch, int st) {
        cpa16(&Ah[st][ar * 12 + ah2 * 4], apH + ch * 16);
        cpa16(&Al[st][ar * 12 + ah2 * 4], apL + ch * 16);
        uint32_t* bdst = (bHi ? &Bh[st][bn * 12 + bh2 * 4] : &Bl[st][bn * 12 + bh2 * 4]);
        cpa16(bdst, bp + ch * 16);
        asm volatile("cp.async.commit_group;");
    };

    float acc[2][4][4];
    #pragma unroll
    for (int mi = 0; mi < 2; mi++)
        #pragma unroll
        for (int ni = 0; ni < 4; ni++)
            #pragma unroll
            for (int c = 0; c < 4; c++) acc[mi][ni][c] = 0.f;

    int nCh = Kd >> 4;
    loadChunk(0, 0);
    for (int ch = 0; ch < nCh; ch++) {
        int st = ch & 1;
        if (ch + 1 < nCh) {
            loadChunk(ch + 1, st ^ 1);
            asm volatile("cp.async.wait_group 1;");
        } else {
            asm volatile("cp.async.wait_group 0;");
        }
        __syncthreads();

        uint32_t ahf[2][4], alf[2][4], bhf[4][2], blf[4][2];
        #pragma unroll
        for (int mi = 0; mi < 2; mi++) {
            int mr = wm + mi * 16 + g;
            ahf[mi][0] = Ah[st][mr * 12 + tig];
            ahf[mi][1] = Ah[st][(mr + 8) * 12 + tig];
            ahf[mi][2] = Ah[st][mr * 12 + tig + 4];
            ahf[mi][3] = Ah[st][(mr + 8) * 12 + tig + 4];
            alf[mi][0] = Al[st][mr * 12 + tig];
            alf[mi][1] = Al[st][(mr + 8) * 12 + tig];
            alf[mi][2] = Al[st][mr * 12 + tig + 4];
            alf[mi][3] = Al[st][(mr + 8) * 12 + tig + 4];
        }
        #pragma unroll
        for (int ni = 0; ni < 4; ni++) {
            int nr = wn + ni * 8 + g;
            bhf[ni][0] = Bh[st][nr * 12 + tig];
            bhf[ni][1] = Bh[st][nr * 12 + tig + 4];
            blf[ni][0] = Bl[st][nr * 12 + tig];
            blf[ni][1] = Bl[st][nr * 12 + tig + 4];
        }
        #pragma unroll
        for (int mi = 0; mi < 2; mi++)
            #pragma unroll
            for (int ni = 0; ni < 4; ni++) {
                mma16(acc[mi][ni], ahf[mi], bhf[ni]);
                mma16(acc[mi][ni], ahf[mi], blf[ni]);
                mma16(acc[mi][ni], alf[mi], bhf[ni]);
            }
        __syncthreads();
    }

    // ---- epilogue ----
    #pragma unroll
    for (int ni = 0; ni < 4; ni++) {
        int col = n0 + wn + ni * 8 + 2 * tig;
        float b0 = 0.f, b1 = 0.f;
        if (bias) { b0 = bias[col]; b1 = bias[col + 1]; }
        #pragma unroll
        for (int mi = 0; mi < 2; mi++) {
            int row = m0 + wm + mi * 16 + g;
            float v00 = acc[mi][ni][0] + b0, v01 = acc[mi][ni][1] + b1;
            float v10 = acc[mi][ni][2] + b0, v11 = acc[mi][ni][3] + b1;
            if (SPLITOUT) {
                uint16_t h, l;
                split1(v00, h, l); Ch[(long)row * ldc + col] = h;     Cl[(long)row * ldc + col] = l;
                split1(v01, h, l); Ch[(long)row * ldc + col + 1] = h; Cl[(long)row * ldc + col + 1] = l;
                split1(v10, h, l); Ch[(long)(row + 8) * ldc + col] = h;     Cl[(long)(row + 8) * ldc + col] = l;
                split1(v11, h, l); Ch[(long)(row + 8) * ldc + col + 1] = h; Cl[(long)(row + 8) * ldc + col + 1] = l;
            } else {
                *(float2*)(C + (long)row * ldc + col) = make_float2(v00, v01);
                *(float2*)(C + (long)(row + 8) * ldc + col) = make_float2(v10, v11);
            }
        }
    }
}

// ---------------- transpose x -> xT fp32 + split ----------------
__global__ void transpose_kernel(const float* __restrict__ x)
{
    __shared__ float tile[32][33];
    int pb = blockIdx.x * 32;
    int cb = blockIdx.y * 32;
    int tx = threadIdx.x, ty = threadIdx.y;
    #pragma unroll
    for (int i = 0; i < 32; i += 8)
        tile[ty + i][tx] = x[(long)(cb + ty + i) * PP + pb + tx];
    __syncthreads();
    #pragma unroll
    for (int i = 0; i < 32; i += 8) {
        float v = tile[tx][ty + i];
        long o = (long)(pb + ty + i) * CC + cb + tx;
        g_xT[o] = v;
        uint16_t h, l;
        split1(v, h, l);
        g_xTh[o] = h;
        g_xTl[o] = l;
    }
}

// ---------------- row-sliding depthwise3x3 + LN + GELU ----------------
// block = (half, y, g), thread = channel. 3 loads/pixel, int32 addressing.
__global__ __launch_bounds__(128) void dw_ln_gelu_kernel(
    const float* __restrict__ in, float* __restrict__ outp,
    const float* __restrict__ w, const float* __restrict__ cb,
    const float* __restrict__ gamma, const float* __restrict__ beta,
    long gStride, int pixStride)
{
    int half = blockIdx.x, y = blockIdx.y, g = blockIdx.z;
    int cc = threadIdx.x;
    int warp = cc >> 5, lane = cc & 31;
    const float* base = in + (long)g * gStride + cc;
    float w0 = w[cc * 9 + 0], w1 = w[cc * 9 + 1], w2 = w[cc * 9 + 2];
    float w3 = w[cc * 9 + 3], w4 = w[cc * 9 + 4], w5 = w[cc * 9 + 5];
    float w6 = w[cc * 9 + 6], w7 = w[cc * 9 + 7], w8 = w[cc * 9 + 8];
    float cbv = cb[cc], gv = gamma[cc], bev = beta[cc];
    __shared__ float r1[2][4], r2[2][4];

    int x0 = half * 32;
    float c0[3], c1[3], c2[3];
    auto ldcol = [&](int xx, float* col) {
        if ((unsigned)xx < 64u) {
            #pragma unroll
            for (int dy = 0; dy < 3; dy++) {
                int yy = y + dy - 1;
                col[dy] = ((unsigned)yy < 64u) ? base[(yy * 64 + xx) * pixStride] : 0.f;
            }
        } else { col[0] = col[1] = col[2] = 0.f; }
    };
    ldcol(x0 - 1, c0);
    ldcol(x0, c1);

    for (int i = 0; i < 32; i++) {
        int x = x0 + i;
        ldcol(x + 1, c2);
        float acc = cbv
            + w0 * c0[0] + w1 * c1[0] + w2 * c2[0]
            + w3 * c0[1] + w4 * c1[1] + w5 * c2[1]
            + w6 * c0[2] + w7 * c1[2] + w8 * c2[2];
        float s1 = acc, s2 = acc * acc;
        #pragma unroll
        for (int o = 16; o > 0; o >>= 1) {
            s1 += __shfl_xor_sync(0xffffffffu, s1, o);
            s2 += __shfl_xor_sync(0xffffffffu, s2, o);
        }
        int b = i & 1;
        if (lane == 0) { r1[b][warp] = s1; r2[b][warp] = s2; }
        __syncthreads();
        float t1s = r1[b][0] + r1[b][1] + r1[b][2] + r1[b][3];
        float t2s = r2[b][0] + r2[b][1] + r2[b][2] + r2[b][3];
        float mean = t1s * (1.f / 128.f);
        float var  = fmaxf(t2s * (1.f / 128.f) - mean * mean, 0.f);
        float nv = (acc - mean) * rsqrtf(var + 1e-5f) * gv + bev;
        float ge = 0.5f * nv * (1.f + erff(nv * 0.70710678118654752f));
        outp[((long)g * PP + y * 64 + x) * CGC + cc] = ge;
        c0[0] = c1[0]; c0[1] = c1[1]; c0[2] = c1[2];
        c1[0] = c2[0]; c1[1] = c2[1]; c1[2] = c2[2];
    }
}

// ---------------- offsets + coords; qsel split; qbk dot ----------------
__global__ void offset_kernel(const int* __restrict__ idx, const float* __restrict__ ow3,
                              const float* __restrict__ bk)
{
    int j = blockIdx.x;
    int tid = threadIdx.x;          // 128
    int warp = tid >> 5, lane = tid & 31;
    __shared__ float tv[128];
    __shared__ float offv[18];
    int iy = idx[2 * j], ix = idx[2 * j + 1];
    int p = iy * 64 + ix;

    {
        float4 v = ((const float4*)(g_qT + (long)p * CC))[tid];
        uint32_t h01, l01, h23, l23;
        split2(v.x, v.y, h01, l01);
        split2(v.z, v.w, h23, l23);
        ((uint2*)(g_qselh + (long)j * CC))[tid] = make_uint2(h01, h23);
        ((uint2*)(g_qsell + (long)j * CC))[tid] = make_uint2(l01, l23);
        float4 b = ((const float4*)bk)[tid];
        float s = v.x * b.x + v.y * b.y + v.z * b.z + v.w * b.w;
        #pragma unroll
        for (int o = 8; o > 0; o >>= 1)
            s += __shfl_xor_sync(0xffffffffu, s, o);
        if ((tid & 15) == 0) g_qbk[(long)j * NH + (tid >> 4)] = s;
    }

    for (int g = 0; g < GG; g++) {
        tv[tid] = g_t2[((long)g * PP + p) * CGC + tid];
        __syncthreads();
        for (int o = warp; o < 18; o += 4) {
            float s = 0.f;
            #pragma unroll
            for (int c = lane; c < 128; c += 32)
                s += tv[c] * ow3[o * 128 + c];
            #pragma unroll
            for (int off = 16; off > 0; off >>= 1)
                s += __shfl_xor_sync(0xffffffffu, s, off);
            if (lane == 0) offv[o] = s;
        }
        __syncthreads();
        if (tid < KK) {
            int k = tid, dy = k / 3, dx = k % 3;
            float oy = tanhf(offv[2 * k])     * (1.f / 32.f);
            float ox = tanhf(offv[2 * k + 1]) * (1.f / 32.f);
            int iyc = min(max(iy + dy - 1, 0), 63);
            int ixc = min(max(ix + dx - 1, 0), 63);
            float ry = (iyc + 0.5f) * (1.f / 32.f) - 1.f;
            float rx = (ixc + 0.5f) * (1.f / 32.f) - 1.f;
            float gy = (oy + ry + 1.f) * 31.5f;
            float gx = (ox + rx + 1.f) * 31.5f;
            g_meta[(long)j * NSLOT + g * KK + k] = make_float2(gy, gx);
        }
        __syncthreads();
    }
}

// ---------------- fused bilinear sampler + attention ----------------
__global__ __launch_bounds__(256) void sample_attn_kernel(float* __restrict__ out)
{
    __shared__ float xs_s[NSLOT * CGC];
    __shared__ float qk_s[4096];
    __shared__ float lg[72];
    __shared__ float at[72];
    int j = blockIdx.x, tid = threadIdx.x;  // 256
    int wid = tid >> 5, lane = tid & 31;
    int ct = tid & 127;
    int half = tid >> 7;
    float* xr = out + XR_OFF;
    int myg = ct >> 5;

    #pragma unroll
    for (int i = 0; i < 16; i++)
        qk_s[i * 256 + tid] = g_qk[(long)j * 4096 + i * 256 + tid];

    #pragma unroll 2
    for (int s2 = 0; s2 < 18; s2++) {
        int s = s2 * 2 + half;
        float2 m = g_meta[(long)j * NSLOT + s];
        float gy = m.x, gx = m.y;
        float y0 = floorf(gy), x0 = floorf(gx);
        float wy1 = gy - y0, wy0 = 1.f - wy1;
        float wx1 = gx - x0, wx0 = 1.f - wx1;
        float4 acc = make_float4(0.f, 0.f, 0.f, 0.f);
        #pragma unroll
        for (int t = 0; t < 4; t++) {
            float yy = y0 + (float)(t >> 1);
            float xx = x0 + (float)(t & 1);
            float w = ((t >> 1) ? wy1 : wy0) * ((t & 1) ? wx1 : wx0);
            bool ok = (yy >= 0.f) && (yy <= 63.f) && (xx >= 0.f) && (xx <= 63.f);
            if (ok && w != 0.f) {
                int yi = (int)yy, xi = (int)xx;
                const float4* row = (const float4*)(g_xT + (long)(yi * 64 + xi) * CC);
                float4 v = row[ct];
                acc.x += w * v.x; acc.y += w * v.y; acc.z += w * v.z; acc.w += w * v.w;
            }
        }
        ((float4*)(xr + ((long)j * NSLOT + s) * CC))[ct] = acc;
        if ((s / KK) == myg)
            *(float4*)&xs_s[s * CGC + 4 * ct - myg * CGC] = acc;
    }
    __syncthreads();

    // logits: warp wid handles head wid
    {
        #pragma unroll
        for (int k = 0; k < KK; k++) {
            float s = 0.f;
            #pragma unroll
            for (int i = 0; i < 16; i++) {
                int cc = (i & 3) * 32 + lane;
                s += qk_s[wid * 512 + i * 32 + lane]
                   * xs_s[((i >> 2) * KK + k) * CGC + cc];
            }
            #pragma unroll
            for (int off = 16; off > 0; off >>= 1)
                s += __shfl_xor_sync(0xffffffffu, s, off);
            if (lane == 0)
                lg[wid * KK + k] = (s + g_qbk[(long)j * NH + wid]) * 0.125f;
        }
    }
    __syncthreads();

    if (tid < NH) {
        int h = tid;
        float mx = -1e30f;
        #pragma unroll
        for (int k = 0; k < KK; k++) mx = fmaxf(mx, lg[h * KK + k]);
        float e[KK], sm = 0.f;
        #pragma unroll
        for (int k = 0; k < KK; k++) { e[k] = expf(lg[h * KK + k] - mx); sm += e[k]; }
        float inv = 1.f / sm;
        #pragma unroll
        for (int k = 0; k < KK; k++) {
            float a = e[k] * inv;
            at[h * KK + k] = a;
            out[ATT_OFF + (long)h * NPT * KK + (long)j * KK + k] = a;
        }
    }
    __syncthreads();

    #pragma unroll
    for (int i = 0; i < 16; i++) {
        int o = i * 256 + tid;
        int h = o >> 9, c = o & 511, g = c >> 7, cc = c & 127;
        float s = 0.f;
        #pragma unroll
        for (int k = 0; k < KK; k++)
            s += at[h * KK + k] * xs_s[(g * KK + k) * CGC + cc];
        uint16_t hh, ll;
        split1(s, hh, ll);
        g_xsh[(long)j * 4096 + o] = hh;
        g_xsl[(long)j * 4096 + o] = ll;
    }
}

// ---------------- sigmoid of selected logit ----------------
__global__ void sig_kernel(const int* __restrict__ labels, float* __restrict__ out)
{
    int j = blockIdx.x * blockDim.x + threadIdx.x;
    if (j < NPT) {
        float v = out[(long)j * CC + labels[j]];
        out[SIG_OFF + j] = 1.f / (1.f + expf(-v));
    }
}

// ---------------- host ----------------
extern "C" void kernel_launch(void* const* d_in, const int* in_sizes, int n_in,
                              void* d_out, int out_size)
{
    const float* x   = (const float*)d_in[0];
    const int*   idx = (const int*)  d_in[1];
    const int*   lab = (const int*)  d_in[2];
    const float* wq  = (const float*)d_in[3];
    const float* bq  = (const float*)d_in[4];
    const float* wk  = (const float*)d_in[5];
    const float* bk  = (const float*)d_in[6];
    const float* wv  = (const float*)d_in[7];
    const float* bv  = (const float*)d_in[8];
    const float* wo  = (const float*)d_in[9];
    const float* bo  = (const float*)d_in[10];
    const float* ow1 = (const float*)d_in[11];
    const float* ob1 = (const float*)d_in[12];
    const float* g1  = (const float*)d_in[13];
    const float* b1  = (const float*)d_in[14];
    const float* ow2 = (const float*)d_in[15];
    const float* ob2 = (const float*)d_in[16];
    const float* g2  = (const float*)d_in[17];
    const float* b2  = (const float*)d_in[18];
    const float* ow3 = (const float*)d_in[19];
    float* out = (float*)d_out;

    float *qT, *t1, *t2, *qk;
    uint16_t *xTh, *xTl, *qsh, *qsl, *xsh, *xsl, *oth, *otl, *wh, *wl;
    cudaGetSymbolAddress((void**)&qT,  g_qT);
    cudaGetSymbolAddress((void**)&t1,  g_t1);
    cudaGetSymbolAddress((void**)&t2,  g_t2);
    cudaGetSymbolAddress((void**)&qk,  g_qk);
    cudaGetSymbolAddress((void**)&xTh, g_xTh);
    cudaGetSymbolAddress((void**)&xTl, g_xTl);
    cudaGetSymbolAddress((void**)&qsh, g_qselh);
    cudaGetSymbolAddress((void**)&qsl, g_qsell);
    cudaGetSymbolAddress((void**)&xsh, g_xsh);
    cudaGetSymbolAddress((void**)&xsl, g_xsl);
    cudaGetSymbolAddress((void**)&oth, g_outTh);
    cudaGetSymbolAddress((void**)&otl, g_outTl);
    cudaGetSymbolAddress((void**)&wh,  g_wh);
    cudaGetSymbolAddress((void**)&wl,  g_wl);
    uint16_t *wqh = wh,            *wql = wl;
    uint16_t *wvh = wh + 262144,   *wvl = wl + 262144;
    uint16_t *woh = wh + 524288,   *wol = wl + 524288;
    uint16_t *wkh = wh + 786432,   *wkl = wl + 786432;   // wkT layout

    // 0) weight split + wk transpose-split
    split_w_kernel<<<1536, 256>>>(wq, wv, wo);
    wkT_kernel<<<dim3(16, 16), dim3(32, 8)>>>(wk);

    // 1) x -> xT fp32 + split
    transpose_kernel<<<dim3(128, 16), dim3(32, 8)>>>(x);

    // 2) qT = xT @ wq^T + bq
    gemm2_kernel<0><<<dim3(8, 32, 1), 256>>>(xTh, xTl, wqh, wql,
        qT, nullptr, nullptr, bq, CC, CC, CC, CC, 0, 0, 0, 0);

    // 3) two depthwise+LN+GELU stages (row-sliding)
    dw_ln_gelu_kernel<<<dim3(2, 64, 4), 128>>>(qT, t1, ow1, ob1, g1, b1,
        (long)CGC, CC);
    dw_ln_gelu_kernel<<<dim3(2, 64, 4), 128>>>(t1, t2, ow2, ob2, g2, b2,
        (long)PP * CGC, CGC);

    // 4) offsets -> coords; qsel split; qbk
    offset_kernel<<<NPT, 128>>>(idx, ow3, bk);

    // 5) qk = q_sel_h @ wkT_h (8 batched, Kd=64)
    gemm2_kernel<0><<<dim3(8, 16, 8), 256>>>(qsh, qsl, wkh, wkl,
        qk, nullptr, nullptr, nullptr, DH, CC, DH, 4096, 64, 32768, 512, 0);

    // 6) fused sampling + attention
    sample_attn_kernel<<<NPT, 256>>>(out);

    // 7) outT = xsagg_h @ wv_h^T + bv (8 batched, split output)
    gemm2_kernel<1><<<dim3(1, 16, 8), 256>>>(xsh, xsl, wvh, wvl,
        nullptr, oth, otl, bv, CC, 4096, CC, CC, 512, 32768, 64, 64);

    // 8) y = outT @ wo^T + bo
    gemm2_kernel<0><<<dim3(8, 16, 1), 256>>>(oth, otl, woh, wol,
        out, nullptr, nullptr, bo, CC, CC, CC, CC, 0, 0, 0, 0);

    // 9) sig
    sig_kernel<<<8, 256>>>(lab, out);
}